// round 1
// baseline (speedup 1.0000x reference)
#include <cuda_runtime.h>
#include <math.h>

// Problem constants
#define BQ   2
#define TT   4096
#define CC   2048
#define DD   64
#define MTOK (BQ*TT)      // 8192 tokens
#define LCH  32           // chunk length for WKV scan
#define NCH  (TT/LCH)     // 128 chunks per batch

// ---------------- device scratch (no allocations allowed) ----------------
__device__ float g_y [MTOK*160];         // tanh mix features
__device__ float g_r [MTOK*DD];
__device__ float g_k [MTOK*DD];
__device__ float g_v [MTOK*DD];
__device__ float g_gv[MTOK*DD];          // silu(g)
__device__ float g_w [MTOK*DD];          // logw = -exp(w)
__device__ float g_M [BQ*NCH*DD*DD];     // per-chunk outer-product sums
__device__ float g_S [BQ*NCH*DD*DD];     // chunk-start states
__device__ float g_P [BQ*NCH*DD];        // per-chunk decay e^{cum w}
__device__ float g_o [MTOK*DD];          // wkv outputs

// =====================================================================
// K1: y = tanh( (hs + xx*maa_x) @ w1 ),  M=8192, N=160, K=2048
// Tile: BM=64, BN=160, BK=32.  xx computed on the fly (prev row - cur row).
// =====================================================================
__global__ __launch_bounds__(256,1) void k1_mix(
    const float* __restrict__ hs, const float* __restrict__ shift,
    const float* __restrict__ maa_x, const float* __restrict__ w1)
{
    __shared__ float sA[32][65];     // [kk][row], padded
    __shared__ float sB[32][160];    // [kk][n]
    const int tid = threadIdx.x;
    const int m0  = blockIdx.x * 64;
    const int ty  = tid >> 4, tx = tid & 15;     // rows ty*4.., cols tx*10..
    const int kkl = tid & 31, ib = tid >> 5;

    float acc[4][10];
    #pragma unroll
    for (int r = 0; r < 4; r++)
        #pragma unroll
        for (int j = 0; j < 10; j++) acc[r][j] = 0.f;

    for (int k0 = 0; k0 < CC; k0 += 32) {
        #pragma unroll
        for (int r = 0; r < 8; r++) {
            int i = ib + r*8;
            int m = m0 + i;
            int c = k0 + kkl;
            float cur  = hs[(size_t)m*CC + c];
            float prev = ((m & (TT-1)) == 0) ? shift[(m>>12)*CC + c]
                                             : hs[(size_t)(m-1)*CC + c];
            sA[kkl][i] = cur + (prev - cur) * __ldg(&maa_x[c]);
        }
        for (int idx = tid; idx < 32*160; idx += 256) {
            int kk = idx / 160, n = idx - kk*160;
            sB[kk][n] = w1[(size_t)(k0+kk)*160 + n];
        }
        __syncthreads();
        #pragma unroll 2
        for (int kk = 0; kk < 32; kk++) {
            float a[4], b[10];
            #pragma unroll
            for (int r = 0; r < 4; r++) a[r] = sA[kk][ty*4 + r];
            #pragma unroll
            for (int j = 0; j < 10; j++) b[j] = sB[kk][tx*10 + j];
            #pragma unroll
            for (int r = 0; r < 4; r++)
                #pragma unroll
                for (int j = 0; j < 10; j++)
                    acc[r][j] += a[r]*b[j];
        }
        __syncthreads();
    }
    #pragma unroll
    for (int r = 0; r < 4; r++)
        #pragma unroll
        for (int j = 0; j < 10; j++)
            g_y[(size_t)(m0 + ty*4 + r)*160 + tx*10 + j] = tanhf(acc[r][j]);
}

// =====================================================================
// K2: fused  m_f = y @ w2_f  ->  A_f = hs + xx*(maa_f + m_f)  ->
//            5 projections (decay_w1, W_k, W_v, W_r, W_g), N=320 total.
// Then epilogue: k,v,r stored; g -> silu; w -> tanh -> @decay_w2 -> logw.
// Tile: BM=64, BK=32, full N.  162 KB dynamic smem, 1 block/SM.
// =====================================================================
#define K2_SMEM_FLOATS (64*161 + 2*(32*65) + 5*32*32 + 160 + 2*(5*32*65))
#define K2_SMEM_BYTES  (K2_SMEM_FLOATS*4)

__global__ __launch_bounds__(256,1) void k2_proj(
    const float* __restrict__ hs, const float* __restrict__ shift,
    const float* __restrict__ maa_w, const float* __restrict__ maa_k,
    const float* __restrict__ maa_v, const float* __restrict__ maa_r,
    const float* __restrict__ maa_g, const float* __restrict__ w2,
    const float* __restrict__ dw1,  const float* __restrict__ Wk,
    const float* __restrict__ Wv,   const float* __restrict__ Wr,
    const float* __restrict__ Wg,   const float* __restrict__ dw2,
    const float* __restrict__ tdecay)
{
    extern __shared__ float sm[];
    float* y_s   = sm;                     // 64*161
    float* hs_s  = y_s  + 64*161;          // 32*65  [kk][i]
    float* xx_s  = hs_s + 32*65;           // 32*65
    float* w2_s  = xx_s + 32*65;           // 5*32*32 [f][d][kk]
    float* maa_s = w2_s + 5*32*32;         // 160 [f*32+kk]
    float* W_s   = maa_s + 160;            // (f*32+kk)*65 + n
    float* A_s   = W_s  + 5*32*65;         // (f*32+kk)*65 + i
    float* t_s   = A_s;                    // reuse in epilogue (64*65)

    const int tid = threadIdx.x;
    const int m0  = blockIdx.x * 64;
    const int w   = tid >> 5;              // warp id -> rows w*8..w*8+7
    const int c0  = tid & 31;
    const int kkl = tid & 31, ib = tid >> 5;

    for (int idx = tid; idx < 64*160; idx += 256) {
        int i = idx / 160, n = idx - i*160;
        y_s[i*161 + n] = g_y[(size_t)(m0+i)*160 + n];
    }

    float acc[5][8][2];
    #pragma unroll
    for (int f = 0; f < 5; f++)
        #pragma unroll
        for (int r = 0; r < 8; r++) { acc[f][r][0] = 0.f; acc[f][r][1] = 0.f; }

    for (int k0 = 0; k0 < CC; k0 += 32) {
        // hs / xx tile
        #pragma unroll
        for (int r = 0; r < 8; r++) {
            int i = ib + r*8;
            int m = m0 + i;
            int c = k0 + kkl;
            float cur  = hs[(size_t)m*CC + c];
            float prev = ((m & (TT-1)) == 0) ? shift[(m>>12)*CC + c]
                                             : hs[(size_t)(m-1)*CC + c];
            hs_s[kkl*65 + i] = cur;
            xx_s[kkl*65 + i] = prev - cur;
        }
        // w2 chunk [f][d][kk]
        for (int idx = tid; idx < 5*32*32; idx += 256) {
            int f = idx >> 10, rem = idx & 1023, d = rem >> 5, kk = rem & 31;
            w2_s[idx] = w2[(size_t)(f*32 + d)*CC + k0 + kk];
        }
        // maa chunk
        if (tid < 160) {
            int f = tid >> 5, kk = tid & 31;
            const float* mp = (f==0) ? maa_w : (f==1) ? maa_k : (f==2) ? maa_v
                             : (f==3) ? maa_r : maa_g;
            maa_s[tid] = mp[k0 + kk];
        }
        // weight tiles
        {
#define K2_LOADW(F, PTR)                                                   \
            for (int idx = tid; idx < 2048; idx += 256) {                  \
                int kk = idx >> 6, n = idx & 63;                           \
                W_s[((F)*32 + kk)*65 + n] = PTR[(size_t)(k0+kk)*64 + n];   \
            }
            K2_LOADW(0, dw1) K2_LOADW(1, Wk) K2_LOADW(2, Wv)
            K2_LOADW(3, Wr)  K2_LOADW(4, Wg)
#undef K2_LOADW
        }
        __syncthreads();

        // A build: 5*32*64 = 10240 elements, each a 32-MAC dot for m_f
        for (int it = 0; it < 40; it++) {
            int idx = tid + 256*it;
            int f   = idx >> 11;
            int rem = idx & 2047;
            int kk  = rem >> 6, i = rem & 63;
            const float* yrow = y_s + i*161 + f*32;
            const float* wcol = w2_s + f*1024 + kk;
            float mval = 0.f;
            #pragma unroll
            for (int d = 0; d < 32; d++) mval += yrow[d] * wcol[d*32];
            A_s[(f*32 + kk)*65 + i] =
                hs_s[kk*65 + i] + xx_s[kk*65 + i]*(maa_s[f*32 + kk] + mval);
        }
        __syncthreads();

        // accumulate 5 projections
        #pragma unroll 2
        for (int kk = 0; kk < 32; kk++) {
            #pragma unroll
            for (int f = 0; f < 5; f++) {
                const float* Arow = A_s + (f*32 + kk)*65 + w*8;
                float b0 = W_s[(f*32 + kk)*65 + c0];
                float b1 = W_s[(f*32 + kk)*65 + c0 + 32];
                #pragma unroll
                for (int r = 0; r < 8; r++) {
                    float a = Arow[r];
                    acc[f][r][0] += a*b0;
                    acc[f][r][1] += a*b1;
                }
            }
        }
        __syncthreads();
    }

    // epilogue: store k,v,r,silu(g); stash tanh(w-proj) for decay_w2 stage
    #pragma unroll
    for (int r = 0; r < 8; r++) {
        int i = w*8 + r;
        size_t base = (size_t)(m0 + i)*64;
        #pragma unroll
        for (int half = 0; half < 2; half++) {
            int n = c0 + half*32;
            g_k[base + n] = acc[1][r][half];
            g_v[base + n] = acc[2][r][half];
            g_r[base + n] = acc[3][r][half];
            float x = acc[4][r][half];
            g_gv[base + n] = x / (1.f + expf(-x));
            t_s[i*65 + n] = tanhf(acc[0][r][half]);
        }
    }
    __syncthreads();
    {
        int i  = tid >> 2;
        int n0 = (tid & 3) * 16;
        #pragma unroll
        for (int j = 0; j < 16; j++) {
            int n = n0 + j;
            float s = 0.f;
            #pragma unroll
            for (int d = 0; d < 64; d++)
                s += t_s[i*65 + d] * __ldg(&dw2[d*64 + n]);
            g_w[(size_t)(m0 + i)*64 + n] = -expf(__ldg(&tdecay[n]) + s);
        }
    }
}

// =====================================================================
// K3: per chunk (b,c): cumulative logw, chunk decay P, and
//     M = sum_i (k_i * exp(cumL - cum_i)) outer v_i
// =====================================================================
__global__ __launch_bounds__(256,1) void k3_chunk()
{
    __shared__ float k_s[32*64], v_s[32*64], cum_s[32*64], kh_s[32*64];
    const int bc   = blockIdx.x;       // b*128 + c
    const int tok0 = bc * 32;          // contiguous since chunks tile batches
    const int tid  = threadIdx.x;

    for (int idx = tid; idx < 2048; idx += 256) {
        size_t g = (size_t)tok0*64 + idx;
        k_s[idx]   = g_k[g];
        v_s[idx]   = g_v[g];
        cum_s[idx] = g_w[g];
    }
    __syncthreads();
    if (tid < 64) {
        float c = 0.f;
        for (int i = 0; i < 32; i++) { c += cum_s[i*64 + tid]; cum_s[i*64 + tid] = c; }
        g_P[bc*64 + tid] = expf(c);
        for (int i = 0; i < 32; i++)
            kh_s[i*64 + tid] = k_s[i*64 + tid] * expf(c - cum_s[i*64 + tid]);
    }
    __syncthreads();
    for (int it = 0; it < 16; it++) {
        int e  = tid + 256*it;
        int dk = e >> 6, dv = e & 63;
        float s = 0.f;
        #pragma unroll
        for (int i = 0; i < 32; i++)
            s += kh_s[i*64 + dk] * v_s[i*64 + dv];
        g_M[(size_t)bc*4096 + e] = s;
    }
}

// =====================================================================
// K4: inter-chunk scan (sequential over 128 chunks, 1 block per batch)
//     S_{c+1} = diag(P_c) S_c + M_c ;  writes chunk-start states + s_final
// =====================================================================
__global__ __launch_bounds__(1024,1) void k4_scan(
    const float* __restrict__ wkv0, float* __restrict__ out_sf)
{
    const int b  = blockIdx.x;
    const int e  = threadIdx.x * 4;
    const int dk = e >> 6;
    const int ei4 = e >> 2;
    float4 s = *(const float4*)(wkv0 + b*4096 + e);
    const float4* Mp = (const float4*)(g_M + (size_t)b*NCH*4096);
    float4*       Sp = (float4*)      (g_S + (size_t)b*NCH*4096);
    const float*  Pp = g_P + b*NCH*64;

    float4 mq[4]; float pq[4];
    #pragma unroll
    for (int q = 0; q < 4; q++) { mq[q] = Mp[q*1024 + ei4]; pq[q] = Pp[q*64 + dk]; }

    for (int c = 0; c < NCH; c += 4) {
        #pragma unroll
        for (int q = 0; q < 4; q++) {
            Sp[(c+q)*1024 + ei4] = s;                 // state BEFORE chunk c+q
            float p = pq[q]; float4 m = mq[q];
            s.x = s.x*p + m.x;  s.y = s.y*p + m.y;
            s.z = s.z*p + m.z;  s.w = s.w*p + m.w;
            int cn = c + q + 4;
            if (cn < NCH) { mq[q] = Mp[cn*1024 + ei4]; pq[q] = Pp[cn*64 + dk]; }
        }
    }
    *(float4*)(out_sf + b*4096 + e) = s;
}

// =====================================================================
// K5: intra-chunk outputs:
//   o_i = rtil_i @ S_c + sum_{j<i} (rtil_i . ktil_j) v_j + (r_i.(u*k_i)) v_i
// =====================================================================
#define K5_SMEM_FLOATS (4*(32*65) + 64*65 + 32*33 + 32)
#define K5_SMEM_BYTES  (K5_SMEM_FLOATS*4)

__global__ __launch_bounds__(256,1) void k5_intra(const float* __restrict__ faaaa)
{
    extern __shared__ float sm[];
    float* r_s    = sm;                 // 32*65
    float* k_s    = r_s   + 32*65;
    float* v_s    = k_s   + 32*65;
    float* cum_s  = v_s   + 32*65;
    float* S_s    = cum_s + 32*65;      // 64*65
    float* sc_s   = S_s   + 64*65;      // 32*33
    float* diag_s = sc_s  + 32*33;      // 32

    const int bc   = blockIdx.x;
    const int tok0 = bc * 32;
    const int tid  = threadIdx.x;

    for (int idx = tid; idx < 2048; idx += 256) {
        int i = idx >> 6, d = idx & 63;
        size_t g = (size_t)tok0*64 + idx;
        r_s[i*65 + d]   = g_r[g];
        k_s[i*65 + d]   = g_k[g];
        v_s[i*65 + d]   = g_v[g];
        cum_s[i*65 + d] = g_w[g];
    }
    for (int idx = tid; idx < 4096; idx += 256) {
        int dk = idx >> 6, dv = idx & 63;
        S_s[dk*65 + dv] = g_S[(size_t)bc*4096 + idx];
    }
    __syncthreads();
    if (tid < 64) {                               // inclusive prefix of logw
        float c = 0.f;
        for (int i = 0; i < 32; i++) { c += cum_s[i*65 + tid]; cum_s[i*65 + tid] = c; }
    }
    __syncthreads();
    if (tid < 32) {                               // diagonal (u) term
        float s = 0.f;
        #pragma unroll
        for (int d = 0; d < 64; d++)
            s += r_s[tid*65 + d] * __ldg(&faaaa[d]) * k_s[tid*65 + d];
        diag_s[tid] = s;
    }
    __syncthreads();
    for (int idx = tid; idx < 2048; idx += 256) { // rtil, ktil in place
        int i = idx >> 6, d = idx & 63;
        float ce = (i == 0) ? 0.f : cum_s[(i-1)*65 + d];
        r_s[i*65 + d] *= expf(ce);
        k_s[i*65 + d] *= expf(-cum_s[i*65 + d]);
    }
    __syncthreads();
    #pragma unroll
    for (int q = 0; q < 4; q++) {                 // masked score matrix
        int idx = tid + 256*q;
        int i = idx >> 5, j = idx & 31;
        float val;
        if (j < i) {
            float s = 0.f;
            #pragma unroll
            for (int d = 0; d < 64; d++)
                s += r_s[i*65 + d] * k_s[j*65 + d];
            val = s;
        } else {
            val = (j == i) ? diag_s[i] : 0.f;
        }
        sc_s[i*33 + j] = val;
    }
    __syncthreads();
    #pragma unroll
    for (int q = 0; q < 8; q++) {                 // outputs
        int idx = tid + 256*q;
        int i = idx >> 6, dv = idx & 63;
        float o = 0.f;
        #pragma unroll
        for (int j = 0; j < 32; j++)
            o += sc_s[i*33 + j] * v_s[j*65 + dv];
        #pragma unroll
        for (int d = 0; d < 64; d++)
            o += r_s[i*65 + d] * S_s[d*65 + dv];
        g_o[(size_t)tok0*64 + idx] = o;
    }
}

// =====================================================================
// K6: out = (o * g) @ W_o   M=8192, N=2048, K=64.  BM=64, BN=64.
// =====================================================================
__global__ __launch_bounds__(256) void k6_out(
    const float* __restrict__ Wo, float* __restrict__ out)
{
    __shared__ float a_s[64*65];   // [d][i]
    __shared__ float b_s[64*65];   // [d][n]
    const int bm = blockIdx.x * 64;
    const int bn = blockIdx.y * 64;
    const int tid = threadIdx.x;

    for (int idx = tid; idx < 4096; idx += 256) {
        int i = idx >> 6, d = idx & 63;
        a_s[d*65 + i] = g_o[(size_t)(bm+i)*64 + d] * g_gv[(size_t)(bm+i)*64 + d];
        b_s[i*65 + d] = Wo[(size_t)i*CC + bn + d];   // here i plays role of k-row
    }
    __syncthreads();
    const int tx = tid & 15, ty = tid >> 4;
    float acc[4][4];
    #pragma unroll
    for (int r = 0; r < 4; r++)
        #pragma unroll
        for (int j = 0; j < 4; j++) acc[r][j] = 0.f;
    #pragma unroll 4
    for (int d = 0; d < 64; d++) {
        float a[4], b[4];
        #pragma unroll
        for (int r = 0; r < 4; r++) a[r] = a_s[d*65 + ty*4 + r];
        #pragma unroll
        for (int j = 0; j < 4; j++) b[j] = b_s[d*65 + tx*4 + j];
        #pragma unroll
        for (int r = 0; r < 4; r++)
            #pragma unroll
            for (int j = 0; j < 4; j++)
                acc[r][j] += a[r]*b[j];
    }
    #pragma unroll
    for (int r = 0; r < 4; r++)
        #pragma unroll
        for (int j = 0; j < 4; j++)
            out[(size_t)(bm + ty*4 + r)*CC + bn + tx*4 + j] = acc[r][j];
}

// lx = hs[:, -1, :]
__global__ void k7_lx(const float* __restrict__ hs, float* __restrict__ out_lx)
{
    int idx = blockIdx.x*blockDim.x + threadIdx.x;   // B*C = 4096
    int b = idx >> 11, c = idx & 2047;
    out_lx[idx] = hs[((size_t)b*TT + (TT-1))*CC + c];
}

// =====================================================================
extern "C" void kernel_launch(void* const* d_in, const int* in_sizes, int n_in,
                              void* d_out, int out_size)
{
    (void)in_sizes; (void)n_in; (void)out_size;
    const float* hs     = (const float*)d_in[0];
    const float* shift  = (const float*)d_in[1];
    const float* wkv0   = (const float*)d_in[2];
    const float* maa_x  = (const float*)d_in[3];
    const float* maa_w  = (const float*)d_in[4];
    const float* maa_k  = (const float*)d_in[5];
    const float* maa_v  = (const float*)d_in[6];
    const float* maa_r  = (const float*)d_in[7];
    const float* maa_g  = (const float*)d_in[8];
    const float* w1     = (const float*)d_in[9];
    const float* w2     = (const float*)d_in[10];
    const float* tdecay = (const float*)d_in[11];
    const float* dw1    = (const float*)d_in[12];
    const float* dw2    = (const float*)d_in[13];
    const float* faaaa  = (const float*)d_in[14];
    const float* Wr     = (const float*)d_in[15];
    const float* Wk     = (const float*)d_in[16];
    const float* Wv     = (const float*)d_in[17];
    const float* Wg     = (const float*)d_in[18];
    const float* Wo     = (const float*)d_in[19];
    float* out = (float*)d_out;

    const size_t OFF_LX = (size_t)BQ*TT*CC;        // 16777216
    const size_t OFF_SF = OFF_LX + (size_t)BQ*CC;  // +4096

    cudaFuncSetAttribute(k2_proj,  cudaFuncAttributeMaxDynamicSharedMemorySize, K2_SMEM_BYTES);
    cudaFuncSetAttribute(k5_intra, cudaFuncAttributeMaxDynamicSharedMemorySize, K5_SMEM_BYTES);

    k1_mix <<<128, 256>>>(hs, shift, maa_x, w1);
    k2_proj<<<128, 256, K2_SMEM_BYTES>>>(hs, shift, maa_w, maa_k, maa_v, maa_r,
                                         maa_g, w2, dw1, Wk, Wv, Wr, Wg, dw2, tdecay);
    k3_chunk<<<BQ*NCH, 256>>>();
    k4_scan <<<BQ, 1024>>>(wkv0, out + OFF_SF);
    k5_intra<<<BQ*NCH, 256, K5_SMEM_BYTES>>>(faaaa);
    k6_out  <<<dim3(MTOK/64, CC/64), 256>>>(Wo, out);
    k7_lx   <<<8, 512>>>(hs, out + OFF_LX);
}

// round 4
// speedup vs baseline: 1.5802x; 1.5802x over previous
#include <cuda_runtime.h>
#include <math.h>

// Problem constants
#define BQ   2
#define TT   4096
#define CC   2048
#define DD   64
#define MTOK (BQ*TT)      // 8192 tokens
#define LCH  32           // chunk length for WKV scan
#define NCH  (TT/LCH)     // 128 chunks per batch

// ---------------- device scratch (no allocations allowed) ----------------
__device__ __align__(16) float g_y [MTOK*160];   // mix features
__device__ __align__(16) float g_r [MTOK*DD];
__device__ __align__(16) float g_k [MTOK*DD];
__device__ __align__(16) float g_v [MTOK*DD];
__device__ __align__(16) float g_gv[MTOK*DD];    // silu(g)
__device__ __align__(16) float g_w [MTOK*DD];    // logw = -exp(w)
__device__ __align__(16) float g_M [BQ*NCH*DD*DD];
__device__ __align__(16) float g_S [BQ*NCH*DD*DD];
__device__ __align__(16) float g_P [BQ*NCH*DD];
__device__ __align__(16) float g_o [MTOK*DD];

// ---------------- tf32 mma helpers ----------------
__device__ __forceinline__ float tf32r(float x) {
    unsigned u;
    asm("cvt.rna.tf32.f32 %0, %1;" : "=r"(u) : "f"(x));
    return __uint_as_float(u);
}
__device__ __forceinline__ void mma8(float* d,
    unsigned a0, unsigned a1, unsigned a2, unsigned a3,
    unsigned b0, unsigned b1)
{
    asm volatile(
        "mma.sync.aligned.m16n8k8.row.col.f32.tf32.tf32.f32 "
        "{%0,%1,%2,%3}, {%4,%5,%6,%7}, {%8,%9}, {%0,%1,%2,%3};"
        : "+f"(d[0]), "+f"(d[1]), "+f"(d[2]), "+f"(d[3])
        : "r"(a0), "r"(a1), "r"(a2), "r"(a3), "r"(b0), "r"(b1));
}
#define FB(x) __float_as_uint(x)

// =====================================================================
// K1 (R1 proven, FFMA): y = (hs + xx*maa_x) @ w1 -> tanh
// =====================================================================
__global__ __launch_bounds__(256,1) void k1_mix(
    const float* __restrict__ hs, const float* __restrict__ shift,
    const float* __restrict__ maa_x, const float* __restrict__ w1)
{
    __shared__ float sA[32][65];     // [kk][row], padded
    __shared__ float sB[32][160];    // [kk][n]
    const int tid = threadIdx.x;
    const int m0  = blockIdx.x * 64;
    const int ty  = tid >> 4, tx = tid & 15;
    const int kkl = tid & 31, ib = tid >> 5;

    float acc[4][10];
    #pragma unroll
    for (int r = 0; r < 4; r++)
        #pragma unroll
        for (int j = 0; j < 10; j++) acc[r][j] = 0.f;

    for (int k0 = 0; k0 < CC; k0 += 32) {
        #pragma unroll
        for (int r = 0; r < 8; r++) {
            int i = ib + r*8;
            int m = m0 + i;
            int c = k0 + kkl;
            float cur  = hs[(size_t)m*CC + c];
            float prev = ((m & (TT-1)) == 0) ? shift[(m>>12)*CC + c]
                                             : hs[(size_t)(m-1)*CC + c];
            sA[kkl][i] = cur + (prev - cur) * __ldg(&maa_x[c]);
        }
        for (int idx = tid; idx < 32*160; idx += 256) {
            int kk = idx / 160, n = idx - kk*160;
            sB[kk][n] = w1[(size_t)(k0+kk)*160 + n];
        }
        __syncthreads();
        #pragma unroll 2
        for (int kk = 0; kk < 32; kk++) {
            float a[4], b[10];
            #pragma unroll
            for (int r = 0; r < 4; r++) a[r] = sA[kk][ty*4 + r];
            #pragma unroll
            for (int j = 0; j < 10; j++) b[j] = sB[kk][tx*10 + j];
            #pragma unroll
            for (int r = 0; r < 4; r++)
                #pragma unroll
                for (int j = 0; j < 10; j++)
                    acc[r][j] += a[r]*b[j];
        }
        __syncthreads();
    }
    #pragma unroll
    for (int r = 0; r < 4; r++)
        #pragma unroll
        for (int j = 0; j < 10; j++)
            g_y[(size_t)(m0 + ty*4 + r)*160 + tx*10 + j] = tanhf(acc[r][j]);
}

// =====================================================================
// K2 (UNDER TEST, tf32 mma): m_f = y @ w2_f -> A_f -> 5 projections.
// =====================================================================
struct K2S {
    float y [64][164];
    float hs[64][36];
    float xx[64][36];
    float w2[5][32][40];   // [f][d][kk]
    float A [5][64][36];   // [f][m][kk]
    float W [5][32][72];   // [f][kk][n]
    float maa[160];
};
static_assert(sizeof(K2S) == 178816, "K2 smem size");
#define K2_SMEM_BYTES ((int)sizeof(K2S))

__global__ __launch_bounds__(256,1) void k2_proj(
    const float* __restrict__ hs, const float* __restrict__ shift,
    const float* __restrict__ maa_w, const float* __restrict__ maa_k,
    const float* __restrict__ maa_v, const float* __restrict__ maa_r,
    const float* __restrict__ maa_g, const float* __restrict__ w2,
    const float* __restrict__ dw1,  const float* __restrict__ Wk,
    const float* __restrict__ Wv,   const float* __restrict__ Wr,
    const float* __restrict__ Wg,   const float* __restrict__ dw2,
    const float* __restrict__ tdecay)
{
    extern __shared__ char smraw[];
    K2S* s = reinterpret_cast<K2S*>(smraw);

    const int tid  = threadIdx.x;
    const int lane = tid & 31, wid = tid >> 5;
    const int gi   = lane >> 2, t = lane & 3;
    const int m0   = blockIdx.x * 64;
    const int mtp  = wid & 3;
    const int nh   = (wid >> 2) * 32;

    for (int idx = tid; idx < 64*160; idx += 256) {
        int i = idx / 160, n = idx - i*160;
        s->y[i][n] = tf32r(g_y[(size_t)(m0+i)*160 + n]);
    }

    float acc[5][4][4];
    #pragma unroll
    for (int f = 0; f < 5; f++)
        #pragma unroll
        for (int j = 0; j < 4; j++)
            #pragma unroll
            for (int e = 0; e < 4; e++) acc[f][j][e] = 0.f;

    for (int k0 = 0; k0 < CC; k0 += 32) {
        for (int idx = tid; idx < 2048; idx += 256) {
            int i = idx >> 5, kk = idx & 31;
            int m = m0 + i, c = k0 + kk;
            float cur  = hs[(size_t)m*CC + c];
            float prev = ((m & (TT-1)) == 0) ? shift[(m>>12)*CC + c]
                                             : hs[(size_t)(m-1)*CC + c];
            s->hs[i][kk] = cur;
            s->xx[i][kk] = prev - cur;
        }
        for (int idx = tid; idx < 5120; idx += 256) {
            int f = idx >> 10, rem = idx & 1023, d = rem >> 5, kk = rem & 31;
            s->w2[f][d][kk] = tf32r(w2[(size_t)(f*32+d)*CC + k0 + kk]);
        }
#define K2_LOADW(F, PTR)                                                     \
        for (int idx = tid; idx < 2048; idx += 256) {                        \
            int kk = idx >> 6, n = idx & 63;                                 \
            s->W[F][kk][n] = tf32r(PTR[(size_t)(k0+kk)*64 + n]);             \
        }
        K2_LOADW(0, dw1) K2_LOADW(1, Wk) K2_LOADW(2, Wv)
        K2_LOADW(3, Wr)  K2_LOADW(4, Wg)
#undef K2_LOADW
        if (tid < 160) {
            int f = tid >> 5, kk = tid & 31;
            const float* mp = (f==0) ? maa_w : (f==1) ? maa_k : (f==2) ? maa_v
                             : (f==3) ? maa_r : maa_g;
            s->maa[tid] = mp[k0 + kk];
        }
        __syncthreads();

        // phase A: m-GEMM + elementwise A build
        #pragma unroll
        for (int q = 0; q < 10; q++) {
            int tix = wid + (q << 3);
            int f   = tix >> 4;
            int r   = tix & 15;
            int mt  = r >> 2;
            int nt  = r & 3;
            float c4[4] = {0.f, 0.f, 0.f, 0.f};
            #pragma unroll
            for (int ks = 0; ks < 4; ks++) {
                unsigned a0 = FB(s->y[mt*16 + gi    ][f*32 + ks*8 + t    ]);
                unsigned a1 = FB(s->y[mt*16 + gi + 8][f*32 + ks*8 + t    ]);
                unsigned a2 = FB(s->y[mt*16 + gi    ][f*32 + ks*8 + t + 4]);
                unsigned a3 = FB(s->y[mt*16 + gi + 8][f*32 + ks*8 + t + 4]);
                unsigned b0 = FB(s->w2[f][ks*8 + t    ][nt*8 + gi]);
                unsigned b1 = FB(s->w2[f][ks*8 + t + 4][nt*8 + gi]);
                mma8(c4, a0,a1,a2,a3, b0,b1);
            }
            #pragma unroll
            for (int e = 0; e < 4; e++) {
                int m  = mt*16 + gi + ((e & 2) ? 8 : 0);
                int kk = nt*8 + t*2 + (e & 1);
                float a = s->hs[m][kk] + s->xx[m][kk]*(s->maa[f*32 + kk] + c4[e]);
                s->A[f][m][kk] = tf32r(a);
            }
        }
        __syncthreads();

        // phase B: projection mma
        #pragma unroll
        for (int f = 0; f < 5; f++) {
            #pragma unroll
            for (int ks = 0; ks < 4; ks++) {
                unsigned a0 = FB(s->A[f][mtp*16 + gi    ][ks*8 + t    ]);
                unsigned a1 = FB(s->A[f][mtp*16 + gi + 8][ks*8 + t    ]);
                unsigned a2 = FB(s->A[f][mtp*16 + gi    ][ks*8 + t + 4]);
                unsigned a3 = FB(s->A[f][mtp*16 + gi + 8][ks*8 + t + 4]);
                #pragma unroll
                for (int j = 0; j < 4; j++) {
                    unsigned b0 = FB(s->W[f][ks*8 + t    ][nh + j*8 + gi]);
                    unsigned b1 = FB(s->W[f][ks*8 + t + 4][nh + j*8 + gi]);
                    mma8(acc[f][j], a0,a1,a2,a3, b0,b1);
                }
            }
        }
        __syncthreads();
    }

    // epilogue
    float* t_s   = &s->A[0][0][0];   // reuse, pitch 68
    float* dw2_s = &s->W[0][0][0];   // reuse, pitch 72
    const int mrow = mtp*16 + gi;
    #pragma unroll
    for (int j = 0; j < 4; j++) {
        int n = nh + j*8 + t*2;
        size_t b0a = (size_t)(m0 + mrow)*64 + n;
        size_t b1a = (size_t)(m0 + mrow + 8)*64 + n;
        g_k[b0a]   = acc[1][j][0]; g_k[b0a+1] = acc[1][j][1];
        g_k[b1a]   = acc[1][j][2]; g_k[b1a+1] = acc[1][j][3];
        g_v[b0a]   = acc[2][j][0]; g_v[b0a+1] = acc[2][j][1];
        g_v[b1a]   = acc[2][j][2]; g_v[b1a+1] = acc[2][j][3];
        g_r[b0a]   = acc[3][j][0]; g_r[b0a+1] = acc[3][j][1];
        g_r[b1a]   = acc[3][j][2]; g_r[b1a+1] = acc[3][j][3];
        #pragma unroll
        for (int e = 0; e < 4; e++) {
            float x = acc[4][j][e];
            float sv = x / (1.f + expf(-x));
            size_t ad = (e & 2) ? b1a : b0a; ad += (e & 1);
            g_gv[ad] = sv;
            int m  = mrow + ((e & 2) ? 8 : 0);
            int nn = n + (e & 1);
            t_s[m*68 + nn] = tf32r(tanhf(acc[0][j][e]));
        }
    }
    for (int idx = tid; idx < 4096; idx += 256) {
        int d = idx >> 6, n = idx & 63;
        dw2_s[d*72 + n] = tf32r(dw2[idx]);
    }
    __syncthreads();

    float acc2[4][4];
    #pragma unroll
    for (int j = 0; j < 4; j++)
        #pragma unroll
        for (int e = 0; e < 4; e++) acc2[j][e] = 0.f;
    #pragma unroll
    for (int ks = 0; ks < 8; ks++) {
        unsigned a0 = FB(t_s[(mtp*16 + gi    )*68 + ks*8 + t    ]);
        unsigned a1 = FB(t_s[(mtp*16 + gi + 8)*68 + ks*8 + t    ]);
        unsigned a2 = FB(t_s[(mtp*16 + gi    )*68 + ks*8 + t + 4]);
        unsigned a3 = FB(t_s[(mtp*16 + gi + 8)*68 + ks*8 + t + 4]);
        #pragma unroll
        for (int j = 0; j < 4; j++) {
            int n0 = nh + j*8;
            unsigned b0 = FB(dw2_s[(ks*8 + t    )*72 + n0 + gi]);
            unsigned b1 = FB(dw2_s[(ks*8 + t + 4)*72 + n0 + gi]);
            mma8(acc2[j], a0,a1,a2,a3, b0,b1);
        }
    }
    #pragma unroll
    for (int j = 0; j < 4; j++) {
        int n = nh + j*8 + t*2;
        #pragma unroll
        for (int e = 0; e < 4; e++) {
            int m  = mrow + ((e & 2) ? 8 : 0);
            int nn = n + (e & 1);
            g_w[(size_t)(m0 + m)*64 + nn] = -expf(__ldg(&tdecay[nn]) + acc2[j][e]);
        }
    }
}

// =====================================================================
// K3 (R1 proven)
// =====================================================================
__global__ __launch_bounds__(256,1) void k3_chunk()
{
    __shared__ float k_s[32*64], v_s[32*64], cum_s[32*64], kh_s[32*64];
    const int bc   = blockIdx.x;
    const int tok0 = bc * 32;
    const int tid  = threadIdx.x;

    for (int idx = tid; idx < 2048; idx += 256) {
        size_t g = (size_t)tok0*64 + idx;
        k_s[idx]   = g_k[g];
        v_s[idx]   = g_v[g];
        cum_s[idx] = g_w[g];
    }
    __syncthreads();
    if (tid < 64) {
        float c = 0.f;
        for (int i = 0; i < 32; i++) { c += cum_s[i*64 + tid]; cum_s[i*64 + tid] = c; }
        g_P[bc*64 + tid] = expf(c);
        for (int i = 0; i < 32; i++)
            kh_s[i*64 + tid] = k_s[i*64 + tid] * expf(c - cum_s[i*64 + tid]);
    }
    __syncthreads();
    for (int it = 0; it < 16; it++) {
        int e  = tid + 256*it;
        int dk = e >> 6, dv = e & 63;
        float s = 0.f;
        #pragma unroll
        for (int i = 0; i < 32; i++)
            s += kh_s[i*64 + dk] * v_s[i*64 + dv];
        g_M[(size_t)bc*4096 + e] = s;
    }
}

// =====================================================================
// K4 (R1 proven): inter-chunk scan, 1 block per batch
// =====================================================================
__global__ __launch_bounds__(1024,1) void k4_scan(
    const float* __restrict__ wkv0, float* __restrict__ out_sf)
{
    const int b  = blockIdx.x;
    const int e  = threadIdx.x * 4;
    const int dk = e >> 6;
    const int ei4 = e >> 2;
    float4 s = *(const float4*)(wkv0 + b*4096 + e);
    const float4* Mp = (const float4*)(g_M + (size_t)b*NCH*4096);
    float4*       Sp = (float4*)      (g_S + (size_t)b*NCH*4096);
    const float*  Pp = g_P + b*NCH*64;

    float4 mq[4]; float pq[4];
    #pragma unroll
    for (int q = 0; q < 4; q++) { mq[q] = Mp[q*1024 + ei4]; pq[q] = Pp[q*64 + dk]; }

    for (int c = 0; c < NCH; c += 4) {
        #pragma unroll
        for (int q = 0; q < 4; q++) {
            Sp[(c+q)*1024 + ei4] = s;
            float p = pq[q]; float4 m = mq[q];
            s.x = s.x*p + m.x;  s.y = s.y*p + m.y;
            s.z = s.z*p + m.z;  s.w = s.w*p + m.w;
            int cn = c + q + 4;
            if (cn < NCH) { mq[q] = Mp[cn*1024 + ei4]; pq[q] = Pp[cn*64 + dk]; }
        }
    }
    *(float4*)(out_sf + b*4096 + e) = s;
}

// =====================================================================
// K5 (R1 proven)
// =====================================================================
#define K5_SMEM_FLOATS (4*(32*65) + 64*65 + 32*33 + 32)
#define K5_SMEM_BYTES  (K5_SMEM_FLOATS*4)

__global__ __launch_bounds__(256,1) void k5_intra(const float* __restrict__ faaaa)
{
    extern __shared__ float sm5[];
    float* r_s    = sm5;
    float* k_s    = r_s   + 32*65;
    float* v_s    = k_s   + 32*65;
    float* cum_s  = v_s   + 32*65;
    float* S_s    = cum_s + 32*65;      // 64*65
    float* sc_s   = S_s   + 64*65;      // 32*33
    float* diag_s = sc_s  + 32*33;      // 32

    const int bc   = blockIdx.x;
    const int tok0 = bc * 32;
    const int tid  = threadIdx.x;

    for (int idx = tid; idx < 2048; idx += 256) {
        int i = idx >> 6, d = idx & 63;
        size_t g = (size_t)tok0*64 + idx;
        r_s[i*65 + d]   = g_r[g];
        k_s[i*65 + d]   = g_k[g];
        v_s[i*65 + d]   = g_v[g];
        cum_s[i*65 + d] = g_w[g];
    }
    for (int idx = tid; idx < 4096; idx += 256) {
        int dk = idx >> 6, dv = idx & 63;
        S_s[dk*65 + dv] = g_S[(size_t)bc*4096 + idx];
    }
    __syncthreads();
    if (tid < 64) {
        float c = 0.f;
        for (int i = 0; i < 32; i++) { c += cum_s[i*65 + tid]; cum_s[i*65 + tid] = c; }
    }
    __syncthreads();
    if (tid < 32) {
        float s = 0.f;
        #pragma unroll
        for (int d = 0; d < 64; d++)
            s += r_s[tid*65 + d] * __ldg(&faaaa[d]) * k_s[tid*65 + d];
        diag_s[tid] = s;
    }
    __syncthreads();
    for (int idx = tid; idx < 2048; idx += 256) {
        int i = idx >> 6, d = idx & 63;
        float ce = (i == 0) ? 0.f : cum_s[(i-1)*65 + d];
        r_s[i*65 + d] *= expf(ce);
        k_s[i*65 + d] *= expf(-cum_s[i*65 + d]);
    }
    __syncthreads();
    #pragma unroll
    for (int q = 0; q < 4; q++) {
        int idx = tid + 256*q;
        int i = idx >> 5, j = idx & 31;
        float val;
        if (j < i) {
            float s = 0.f;
            #pragma unroll
            for (int d = 0; d < 64; d++)
                s += r_s[i*65 + d] * k_s[j*65 + d];
            val = s;
        } else {
            val = (j == i) ? diag_s[i] : 0.f;
        }
        sc_s[i*33 + j] = val;
    }
    __syncthreads();
    #pragma unroll
    for (int q = 0; q < 8; q++) {
        int idx = tid + 256*q;
        int i = idx >> 6, dv = idx & 63;
        float o = 0.f;
        #pragma unroll
        for (int j = 0; j < 32; j++)
            o += sc_s[i*33 + j] * v_s[j*65 + dv];
        #pragma unroll
        for (int d = 0; d < 64; d++)
            o += r_s[i*65 + d] * S_s[d*65 + dv];
        g_o[(size_t)tok0*64 + idx] = o;
    }
}

// =====================================================================
// K6 (R1 proven, FFMA): out = (o * g) @ W_o
// =====================================================================
__global__ __launch_bounds__(256) void k6_out(
    const float* __restrict__ Wo, float* __restrict__ out)
{
    __shared__ float a_s[64*65];   // [d][i]
    __shared__ float b_s[64*65];   // [d][n]
    const int bm = blockIdx.x * 64;
    const int bn = blockIdx.y * 64;
    const int tid = threadIdx.x;

    for (int idx = tid; idx < 4096; idx += 256) {
        int i = idx >> 6, d = idx & 63;
        a_s[d*65 + i] = g_o[(size_t)(bm+i)*64 + d] * g_gv[(size_t)(bm+i)*64 + d];
        b_s[i*65 + d] = Wo[(size_t)i*CC + bn + d];
    }
    __syncthreads();
    const int tx = tid & 15, ty = tid >> 4;
    float acc[4][4];
    #pragma unroll
    for (int r = 0; r < 4; r++)
        #pragma unroll
        for (int j = 0; j < 4; j++) acc[r][j] = 0.f;
    #pragma unroll 4
    for (int d = 0; d < 64; d++) {
        float a[4], b[4];
        #pragma unroll
        for (int r = 0; r < 4; r++) a[r] = a_s[d*65 + ty*4 + r];
        #pragma unroll
        for (int j = 0; j < 4; j++) b[j] = b_s[d*65 + tx*4 + j];
        #pragma unroll
        for (int r = 0; r < 4; r++)
            #pragma unroll
            for (int j = 0; j < 4; j++)
                acc[r][j] += a[r]*b[j];
    }
    #pragma unroll
    for (int r = 0; r < 4; r++)
        #pragma unroll
        for (int j = 0; j < 4; j++)
            out[(size_t)(bm + ty*4 + r)*CC + bn + tx*4 + j] = acc[r][j];
}

// lx = hs[:, -1, :]
__global__ void k7_lx(const float* __restrict__ hs, float* __restrict__ out_lx)
{
    int idx = blockIdx.x*blockDim.x + threadIdx.x;   // B*C = 4096
    int b = idx >> 11, c = idx & 2047;
    out_lx[idx] = hs[((size_t)b*TT + (TT-1))*CC + c];
}

// =====================================================================
extern "C" void kernel_launch(void* const* d_in, const int* in_sizes, int n_in,
                              void* d_out, int out_size)
{
    (void)in_sizes; (void)n_in; (void)out_size;
    const float* hs     = (const float*)d_in[0];
    const float* shift  = (const float*)d_in[1];
    const float* wkv0   = (const float*)d_in[2];
    const float* maa_x  = (const float*)d_in[3];
    const float* maa_w  = (const float*)d_in[4];
    const float* maa_k  = (const float*)d_in[5];
    const float* maa_v  = (const float*)d_in[6];
    const float* maa_r  = (const float*)d_in[7];
    const float* maa_g  = (const float*)d_in[8];
    const float* w1     = (const float*)d_in[9];
    const float* w2     = (const float*)d_in[10];
    const float* tdecay = (const float*)d_in[11];
    const float* dw1    = (const float*)d_in[12];
    const float* dw2    = (const float*)d_in[13];
    const float* faaaa  = (const float*)d_in[14];
    const float* Wr     = (const float*)d_in[15];
    const float* Wk     = (const float*)d_in[16];
    const float* Wv     = (const float*)d_in[17];
    const float* Wg     = (const float*)d_in[18];
    const float* Wo     = (const float*)d_in[19];
    float* out = (float*)d_out;

    const size_t OFF_LX = (size_t)BQ*TT*CC;        // 16777216
    const size_t OFF_SF = OFF_LX + (size_t)BQ*CC;  // +4096

    cudaFuncSetAttribute(k2_proj,  cudaFuncAttributeMaxDynamicSharedMemorySize, K2_SMEM_BYTES);
    cudaFuncSetAttribute(k5_intra, cudaFuncAttributeMaxDynamicSharedMemorySize, K5_SMEM_BYTES);

    k1_mix <<<128, 256>>>(hs, shift, maa_x, w1);
    k2_proj<<<128, 256, K2_SMEM_BYTES>>>(hs, shift, maa_w, maa_k, maa_v, maa_r,
                                         maa_g, w2, dw1, Wk, Wv, Wr, Wg, dw2, tdecay);
    k3_chunk<<<BQ*NCH, 256>>>();
    k4_scan <<<BQ, 1024>>>(wkv0, out + OFF_SF);
    k5_intra<<<BQ*NCH, 256, K5_SMEM_BYTES>>>(faaaa);
    k6_out  <<<dim3(MTOK/64, CC/64), 256>>>(Wo, out);
    k7_lx   <<<8, 512>>>(hs, out + OFF_LX);
}

// round 5
// speedup vs baseline: 1.7838x; 1.1288x over previous
#include <cuda_runtime.h>
#include <math.h>

// Problem constants
#define BQ   2
#define TT   4096
#define CC   2048
#define DD   64
#define MTOK (BQ*TT)      // 8192 tokens
#define LCH  32           // chunk length for WKV scan
#define NCH  (TT/LCH)     // 128 chunks per batch

// ---------------- device scratch (no allocations allowed) ----------------
__device__ __align__(16) float g_y [MTOK*160];   // mix features (tf32-rounded)
__device__ __align__(16) float g_r [MTOK*DD];
__device__ __align__(16) float g_k [MTOK*DD];
__device__ __align__(16) float g_v [MTOK*DD];
__device__ __align__(16) float g_gv[MTOK*DD];    // silu(g)
__device__ __align__(16) float g_w [MTOK*DD];    // logw = -exp(w)
__device__ __align__(16) float g_M [BQ*NCH*DD*DD];
__device__ __align__(16) float g_S [BQ*NCH*DD*DD];
__device__ __align__(16) float g_P [BQ*NCH*DD];
__device__ __align__(16) float g_o [MTOK*DD];

// ---------------- tf32 mma helpers ----------------
__device__ __forceinline__ float tf32r(float x) {
    unsigned u;
    asm("cvt.rna.tf32.f32 %0, %1;" : "=r"(u) : "f"(x));
    return __uint_as_float(u);
}
__device__ __forceinline__ void mma8(float* d,
    unsigned a0, unsigned a1, unsigned a2, unsigned a3,
    unsigned b0, unsigned b1)
{
    asm volatile(
        "mma.sync.aligned.m16n8k8.row.col.f32.tf32.tf32.f32 "
        "{%0,%1,%2,%3}, {%4,%5,%6,%7}, {%8,%9}, {%0,%1,%2,%3};"
        : "+f"(d[0]), "+f"(d[1]), "+f"(d[2]), "+f"(d[3])
        : "r"(a0), "r"(a1), "r"(a2), "r"(a3), "r"(b0), "r"(b1));
}
#define FB(x) __float_as_uint(x)

// =====================================================================
// K1: y = tanh( (hs + xx*maa_x) @ w1 ),  M=8192, N=160, K=2048  (tf32 mma)
// =====================================================================
__global__ __launch_bounds__(256,1) void k1_mix(
    const float* __restrict__ hs, const float* __restrict__ shift,
    const float* __restrict__ maa_x, const float* __restrict__ w1)
{
    __shared__ float x_s [64*36];    // A tile [m][k]
    __shared__ float w1_s[32*168];   // B tile [k][n]
    const int tid  = threadIdx.x;
    const int lane = tid & 31, wid = tid >> 5;
    const int gi   = lane >> 2, t = lane & 3;
    const int m0   = blockIdx.x * 64;
    const int mt   = wid & 3;
    const int nbase= (wid >> 2) * 80;

    float acc[10][4];
    #pragma unroll
    for (int j = 0; j < 10; j++)
        #pragma unroll
        for (int e = 0; e < 4; e++) acc[j][e] = 0.f;

    for (int k0 = 0; k0 < CC; k0 += 32) {
        for (int idx = tid; idx < 2048; idx += 256) {
            int i = idx >> 5, kk = idx & 31;
            int m = m0 + i, c = k0 + kk;
            float cur  = hs[(size_t)m*CC + c];
            float prev = ((m & (TT-1)) == 0) ? shift[(m>>12)*CC + c]
                                             : hs[(size_t)(m-1)*CC + c];
            x_s[i*36 + kk] = tf32r(cur + (prev - cur) * __ldg(&maa_x[c]));
        }
        for (int idx = tid; idx < 5120; idx += 256) {   // 32*160 scalar
            int kk = idx / 160, n = idx - kk*160;
            w1_s[kk*168 + n] = tf32r(w1[(size_t)(k0+kk)*160 + n]);
        }
        __syncthreads();
        #pragma unroll
        for (int ks = 0; ks < 4; ks++) {
            const float* Ab = x_s + (mt*16)*36 + ks*8;
            unsigned a0 = FB(Ab[gi*36 + t]);
            unsigned a1 = FB(Ab[(gi+8)*36 + t]);
            unsigned a2 = FB(Ab[gi*36 + t + 4]);
            unsigned a3 = FB(Ab[(gi+8)*36 + t + 4]);
            #pragma unroll
            for (int j = 0; j < 10; j++) {
                int n0 = nbase + j*8;
                unsigned b0 = FB(w1_s[(ks*8+t)*168 + n0 + gi]);
                unsigned b1 = FB(w1_s[(ks*8+t+4)*168 + n0 + gi]);
                mma8(acc[j], a0,a1,a2,a3, b0,b1);
            }
        }
        __syncthreads();
    }
    const int mrow = m0 + mt*16 + gi;
    #pragma unroll
    for (int j = 0; j < 10; j++) {
        int n = nbase + j*8 + t*2;
        g_y[(size_t)mrow*160 + n]       = tf32r(tanhf(acc[j][0]));
        g_y[(size_t)mrow*160 + n + 1]   = tf32r(tanhf(acc[j][1]));
        g_y[(size_t)(mrow+8)*160 + n]   = tf32r(tanhf(acc[j][2]));
        g_y[(size_t)(mrow+8)*160 + n+1] = tf32r(tanhf(acc[j][3]));
    }
}

// =====================================================================
// K2 (R4 proven, tf32 mma): m_f = y @ w2_f -> A_f -> 5 projections.
// =====================================================================
struct K2S {
    float y [64][164];
    float hs[64][36];
    float xx[64][36];
    float w2[5][32][40];   // [f][d][kk]
    float A [5][64][36];   // [f][m][kk]
    float W [5][32][72];   // [f][kk][n]
    float maa[160];
};
static_assert(sizeof(K2S) == 178816, "K2 smem size");
#define K2_SMEM_BYTES ((int)sizeof(K2S))

__global__ __launch_bounds__(256,1) void k2_proj(
    const float* __restrict__ hs, const float* __restrict__ shift,
    const float* __restrict__ maa_w, const float* __restrict__ maa_k,
    const float* __restrict__ maa_v, const float* __restrict__ maa_r,
    const float* __restrict__ maa_g, const float* __restrict__ w2,
    const float* __restrict__ dw1,  const float* __restrict__ Wk,
    const float* __restrict__ Wv,   const float* __restrict__ Wr,
    const float* __restrict__ Wg,   const float* __restrict__ dw2,
    const float* __restrict__ tdecay)
{
    extern __shared__ char smraw[];
    K2S* s = reinterpret_cast<K2S*>(smraw);

    const int tid  = threadIdx.x;
    const int lane = tid & 31, wid = tid >> 5;
    const int gi   = lane >> 2, t = lane & 3;
    const int m0   = blockIdx.x * 64;
    const int mtp  = wid & 3;
    const int nh   = (wid >> 2) * 32;

    for (int idx = tid; idx < 64*160; idx += 256) {
        int i = idx / 160, n = idx - i*160;
        s->y[i][n] = g_y[(size_t)(m0+i)*160 + n];   // already tf32-rounded
    }

    float acc[5][4][4];
    #pragma unroll
    for (int f = 0; f < 5; f++)
        #pragma unroll
        for (int j = 0; j < 4; j++)
            #pragma unroll
            for (int e = 0; e < 4; e++) acc[f][j][e] = 0.f;

    for (int k0 = 0; k0 < CC; k0 += 32) {
        for (int idx = tid; idx < 2048; idx += 256) {
            int i = idx >> 5, kk = idx & 31;
            int m = m0 + i, c = k0 + kk;
            float cur  = hs[(size_t)m*CC + c];
            float prev = ((m & (TT-1)) == 0) ? shift[(m>>12)*CC + c]
                                             : hs[(size_t)(m-1)*CC + c];
            s->hs[i][kk] = cur;
            s->xx[i][kk] = prev - cur;
        }
        for (int idx = tid; idx < 5120; idx += 256) {
            int f = idx >> 10, rem = idx & 1023, d = rem >> 5, kk = rem & 31;
            s->w2[f][d][kk] = tf32r(w2[(size_t)(f*32+d)*CC + k0 + kk]);
        }
#define K2_LOADW(F, PTR)                                                     \
        for (int idx = tid; idx < 2048; idx += 256) {                        \
            int kk = idx >> 6, n = idx & 63;                                 \
            s->W[F][kk][n] = tf32r(PTR[(size_t)(k0+kk)*64 + n]);             \
        }
        K2_LOADW(0, dw1) K2_LOADW(1, Wk) K2_LOADW(2, Wv)
        K2_LOADW(3, Wr)  K2_LOADW(4, Wg)
#undef K2_LOADW
        if (tid < 160) {
            int f = tid >> 5, kk = tid & 31;
            const float* mp = (f==0) ? maa_w : (f==1) ? maa_k : (f==2) ? maa_v
                             : (f==3) ? maa_r : maa_g;
            s->maa[tid] = mp[k0 + kk];
        }
        __syncthreads();

        // phase A: m-GEMM + elementwise A build
        #pragma unroll
        for (int q = 0; q < 10; q++) {
            int tix = wid + (q << 3);
            int f   = tix >> 4;
            int r   = tix & 15;
            int mt  = r >> 2;
            int nt  = r & 3;
            float c4[4] = {0.f, 0.f, 0.f, 0.f};
            #pragma unroll
            for (int ks = 0; ks < 4; ks++) {
                unsigned a0 = FB(s->y[mt*16 + gi    ][f*32 + ks*8 + t    ]);
                unsigned a1 = FB(s->y[mt*16 + gi + 8][f*32 + ks*8 + t    ]);
                unsigned a2 = FB(s->y[mt*16 + gi    ][f*32 + ks*8 + t + 4]);
                unsigned a3 = FB(s->y[mt*16 + gi + 8][f*32 + ks*8 + t + 4]);
                unsigned b0 = FB(s->w2[f][ks*8 + t    ][nt*8 + gi]);
                unsigned b1 = FB(s->w2[f][ks*8 + t + 4][nt*8 + gi]);
                mma8(c4, a0,a1,a2,a3, b0,b1);
            }
            #pragma unroll
            for (int e = 0; e < 4; e++) {
                int m  = mt*16 + gi + ((e & 2) ? 8 : 0);
                int kk = nt*8 + t*2 + (e & 1);
                float a = s->hs[m][kk] + s->xx[m][kk]*(s->maa[f*32 + kk] + c4[e]);
                s->A[f][m][kk] = tf32r(a);
            }
        }
        __syncthreads();

        // phase B: projection mma
        #pragma unroll
        for (int f = 0; f < 5; f++) {
            #pragma unroll
            for (int ks = 0; ks < 4; ks++) {
                unsigned a0 = FB(s->A[f][mtp*16 + gi    ][ks*8 + t    ]);
                unsigned a1 = FB(s->A[f][mtp*16 + gi + 8][ks*8 + t    ]);
                unsigned a2 = FB(s->A[f][mtp*16 + gi    ][ks*8 + t + 4]);
                unsigned a3 = FB(s->A[f][mtp*16 + gi + 8][ks*8 + t + 4]);
                #pragma unroll
                for (int j = 0; j < 4; j++) {
                    unsigned b0 = FB(s->W[f][ks*8 + t    ][nh + j*8 + gi]);
                    unsigned b1 = FB(s->W[f][ks*8 + t + 4][nh + j*8 + gi]);
                    mma8(acc[f][j], a0,a1,a2,a3, b0,b1);
                }
            }
        }
        __syncthreads();
    }

    // epilogue
    float* t_s   = &s->A[0][0][0];   // reuse, pitch 68
    float* dw2_s = &s->W[0][0][0];   // reuse, pitch 72
    const int mrow = mtp*16 + gi;
    #pragma unroll
    for (int j = 0; j < 4; j++) {
        int n = nh + j*8 + t*2;
        size_t b0a = (size_t)(m0 + mrow)*64 + n;
        size_t b1a = (size_t)(m0 + mrow + 8)*64 + n;
        g_k[b0a]   = acc[1][j][0]; g_k[b0a+1] = acc[1][j][1];
        g_k[b1a]   = acc[1][j][2]; g_k[b1a+1] = acc[1][j][3];
        g_v[b0a]   = acc[2][j][0]; g_v[b0a+1] = acc[2][j][1];
        g_v[b1a]   = acc[2][j][2]; g_v[b1a+1] = acc[2][j][3];
        g_r[b0a]   = acc[3][j][0]; g_r[b0a+1] = acc[3][j][1];
        g_r[b1a]   = acc[3][j][2]; g_r[b1a+1] = acc[3][j][3];
        #pragma unroll
        for (int e = 0; e < 4; e++) {
            float x = acc[4][j][e];
            float sv = x / (1.f + expf(-x));
            size_t ad = (e & 2) ? b1a : b0a; ad += (e & 1);
            g_gv[ad] = sv;
            int m  = mrow + ((e & 2) ? 8 : 0);
            int nn = n + (e & 1);
            t_s[m*68 + nn] = tf32r(tanhf(acc[0][j][e]));
        }
    }
    for (int idx = tid; idx < 4096; idx += 256) {
        int d = idx >> 6, n = idx & 63;
        dw2_s[d*72 + n] = tf32r(dw2[idx]);
    }
    __syncthreads();

    float acc2[4][4];
    #pragma unroll
    for (int j = 0; j < 4; j++)
        #pragma unroll
        for (int e = 0; e < 4; e++) acc2[j][e] = 0.f;
    #pragma unroll
    for (int ks = 0; ks < 8; ks++) {
        unsigned a0 = FB(t_s[(mtp*16 + gi    )*68 + ks*8 + t    ]);
        unsigned a1 = FB(t_s[(mtp*16 + gi + 8)*68 + ks*8 + t    ]);
        unsigned a2 = FB(t_s[(mtp*16 + gi    )*68 + ks*8 + t + 4]);
        unsigned a3 = FB(t_s[(mtp*16 + gi + 8)*68 + ks*8 + t + 4]);
        #pragma unroll
        for (int j = 0; j < 4; j++) {
            int n0 = nh + j*8;
            unsigned b0 = FB(dw2_s[(ks*8 + t    )*72 + n0 + gi]);
            unsigned b1 = FB(dw2_s[(ks*8 + t + 4)*72 + n0 + gi]);
            mma8(acc2[j], a0,a1,a2,a3, b0,b1);
        }
    }
    #pragma unroll
    for (int j = 0; j < 4; j++) {
        int n = nh + j*8 + t*2;
        #pragma unroll
        for (int e = 0; e < 4; e++) {
            int m  = mrow + ((e & 2) ? 8 : 0);
            int nn = n + (e & 1);
            g_w[(size_t)(m0 + m)*64 + nn] = -expf(__ldg(&tdecay[nn]) + acc2[j][e]);
        }
    }
}

// =====================================================================
// K3 (proven)
// =====================================================================
__global__ __launch_bounds__(256,1) void k3_chunk()
{
    __shared__ float k_s[32*64], v_s[32*64], cum_s[32*64], kh_s[32*64];
    const int bc   = blockIdx.x;
    const int tok0 = bc * 32;
    const int tid  = threadIdx.x;

    for (int idx = tid; idx < 2048; idx += 256) {
        size_t g = (size_t)tok0*64 + idx;
        k_s[idx]   = g_k[g];
        v_s[idx]   = g_v[g];
        cum_s[idx] = g_w[g];
    }
    __syncthreads();
    if (tid < 64) {
        float c = 0.f;
        for (int i = 0; i < 32; i++) { c += cum_s[i*64 + tid]; cum_s[i*64 + tid] = c; }
        g_P[bc*64 + tid] = expf(c);
        for (int i = 0; i < 32; i++)
            kh_s[i*64 + tid] = k_s[i*64 + tid] * expf(c - cum_s[i*64 + tid]);
    }
    __syncthreads();
    for (int it = 0; it < 16; it++) {
        int e  = tid + 256*it;
        int dk = e >> 6, dv = e & 63;
        float s = 0.f;
        #pragma unroll
        for (int i = 0; i < 32; i++)
            s += kh_s[i*64 + dk] * v_s[i*64 + dv];
        g_M[(size_t)bc*4096 + e] = s;
    }
}

// =====================================================================
// K4: inter-chunk scan — one scalar element per thread, 32 blocks.
// =====================================================================
__global__ __launch_bounds__(256,1) void k4_scan(
    const float* __restrict__ wkv0, float* __restrict__ out_sf)
{
    const int e  = blockIdx.x*256 + threadIdx.x;     // 0..8191
    const int b  = e >> 12, eb = e & 4095, dk = eb >> 6;
    float sv = wkv0[e];
    const float* Mp = g_M + (size_t)b*NCH*4096 + eb;
    const float* Pp = g_P + b*NCH*64 + dk;
    float*       Sp = g_S + (size_t)b*NCH*4096 + eb;

    float mq[4], pq[4];
    #pragma unroll
    for (int q = 0; q < 4; q++) { mq[q] = Mp[q*4096]; pq[q] = Pp[q*64]; }

    for (int c = 0; c < NCH; c += 4) {
        #pragma unroll
        for (int q = 0; q < 4; q++) {
            Sp[(size_t)(c+q)*4096] = sv;
            sv = sv*pq[q] + mq[q];
            int cn = c + q + 4;
            if (cn < NCH) { mq[q] = Mp[(size_t)cn*4096]; pq[q] = Pp[cn*64]; }
        }
    }
    out_sf[e] = sv;
}

// =====================================================================
// K5 (proven)
// =====================================================================
#define K5_SMEM_FLOATS (4*(32*65) + 64*65 + 32*33 + 32)
#define K5_SMEM_BYTES  (K5_SMEM_FLOATS*4)

__global__ __launch_bounds__(256,1) void k5_intra(const float* __restrict__ faaaa)
{
    extern __shared__ float sm5[];
    float* r_s    = sm5;
    float* k_s    = r_s   + 32*65;
    float* v_s    = k_s   + 32*65;
    float* cum_s  = v_s   + 32*65;
    float* S_s    = cum_s + 32*65;      // 64*65
    float* sc_s   = S_s   + 64*65;      // 32*33
    float* diag_s = sc_s  + 32*33;      // 32

    const int bc   = blockIdx.x;
    const int tok0 = bc * 32;
    const int tid  = threadIdx.x;

    for (int idx = tid; idx < 2048; idx += 256) {
        int i = idx >> 6, d = idx & 63;
        size_t g = (size_t)tok0*64 + idx;
        r_s[i*65 + d]   = g_r[g];
        k_s[i*65 + d]   = g_k[g];
        v_s[i*65 + d]   = g_v[g];
        cum_s[i*65 + d] = g_w[g];
    }
    for (int idx = tid; idx < 4096; idx += 256) {
        int dk = idx >> 6, dv = idx & 63;
        S_s[dk*65 + dv] = g_S[(size_t)bc*4096 + idx];
    }
    __syncthreads();
    if (tid < 64) {
        float c = 0.f;
        for (int i = 0; i < 32; i++) { c += cum_s[i*65 + tid]; cum_s[i*65 + tid] = c; }
    }
    __syncthreads();
    if (tid < 32) {
        float s = 0.f;
        #pragma unroll
        for (int d = 0; d < 64; d++)
            s += r_s[tid*65 + d] * __ldg(&faaaa[d]) * k_s[tid*65 + d];
        diag_s[tid] = s;
    }
    __syncthreads();
    for (int idx = tid; idx < 2048; idx += 256) {
        int i = idx >> 6, d = idx & 63;
        float ce = (i == 0) ? 0.f : cum_s[(i-1)*65 + d];
        r_s[i*65 + d] *= expf(ce);
        k_s[i*65 + d] *= expf(-cum_s[i*65 + d]);
    }
    __syncthreads();
    #pragma unroll
    for (int q = 0; q < 4; q++) {
        int idx = tid + 256*q;
        int i = idx >> 5, j = idx & 31;
        float val;
        if (j < i) {
            float s = 0.f;
            #pragma unroll
            for (int d = 0; d < 64; d++)
                s += r_s[i*65 + d] * k_s[j*65 + d];
            val = s;
        } else {
            val = (j == i) ? diag_s[i] : 0.f;
        }
        sc_s[i*33 + j] = val;
    }
    __syncthreads();
    #pragma unroll
    for (int q = 0; q < 8; q++) {
        int idx = tid + 256*q;
        int i = idx >> 6, dv = idx & 63;
        float o = 0.f;
        #pragma unroll
        for (int j = 0; j < 32; j++)
            o += sc_s[i*33 + j] * v_s[j*65 + dv];
        #pragma unroll
        for (int d = 0; d < 64; d++)
            o += r_s[i*65 + d] * S_s[d*65 + dv];
        g_o[(size_t)tok0*64 + idx] = o;
    }
}

// =====================================================================
// K6: out = (o * g) @ W_o  via tf32 mma.  Block tile 128x128, K=64.
// NOTE: dynamic smem — launch MUST pass K6_SMEM_BYTES.
// =====================================================================
#define K6_SMEM_BYTES ((128*68 + 64*136)*4)
__global__ __launch_bounds__(256,1) void k6_out(
    const float* __restrict__ Wo, float* __restrict__ out)
{
    extern __shared__ float sm6[];
    float* a_s = sm6;               // [128][68]
    float* b_s = a_s + 128*68;      // [64][136]

    const int tid  = threadIdx.x;
    const int lane = tid & 31, wid = tid >> 5;
    const int gi   = lane >> 2, t = lane & 3;
    const int bm = blockIdx.x * 128, bn = blockIdx.y * 128;

    for (int idx = tid; idx < 8192; idx += 256) {     // 128*64 scalar
        int i = idx >> 6, d = idx & 63;
        size_t g = (size_t)(bm+i)*64 + d;
        a_s[i*68 + d] = tf32r(g_o[g] * g_gv[g]);
    }
    for (int idx = tid; idx < 8192; idx += 256) {     // 64*128 scalar
        int dd = idx >> 7, n = idx & 127;
        b_s[dd*136 + n] = tf32r(Wo[(size_t)dd*CC + bn + n]);
    }
    __syncthreads();

    const int rb = (wid & 3) * 32;
    const int n0 = (wid >> 2) * 64;
    float acc[2][8][4];
    #pragma unroll
    for (int mi = 0; mi < 2; mi++)
        #pragma unroll
        for (int j = 0; j < 8; j++)
            #pragma unroll
            for (int e = 0; e < 4; e++) acc[mi][j][e] = 0.f;

    #pragma unroll
    for (int ks = 0; ks < 8; ks++) {
        unsigned a[2][4];
        #pragma unroll
        for (int mi = 0; mi < 2; mi++) {
            const float* Ab = a_s + (rb + mi*16)*68 + ks*8;
            a[mi][0] = FB(Ab[gi*68 + t]);
            a[mi][1] = FB(Ab[(gi+8)*68 + t]);
            a[mi][2] = FB(Ab[gi*68 + t + 4]);
            a[mi][3] = FB(Ab[(gi+8)*68 + t + 4]);
        }
        #pragma unroll
        for (int j = 0; j < 8; j++) {
            unsigned b0 = FB(b_s[(ks*8+t)*136 + n0 + j*8 + gi]);
            unsigned b1 = FB(b_s[(ks*8+t+4)*136 + n0 + j*8 + gi]);
            mma8(acc[0][j], a[0][0],a[0][1],a[0][2],a[0][3], b0,b1);
            mma8(acc[1][j], a[1][0],a[1][1],a[1][2],a[1][3], b0,b1);
        }
    }
    #pragma unroll
    for (int mi = 0; mi < 2; mi++)
        #pragma unroll
        for (int j = 0; j < 8; j++) {
            int m = bm + rb + mi*16 + gi;
            int n = bn + n0 + j*8 + t*2;
            out[(size_t)m*CC + n]       = acc[mi][j][0];
            out[(size_t)m*CC + n + 1]   = acc[mi][j][1];
            out[(size_t)(m+8)*CC + n]   = acc[mi][j][2];
            out[(size_t)(m+8)*CC + n+1] = acc[mi][j][3];
        }
}

// lx = hs[:, -1, :]
__global__ void k7_lx(const float* __restrict__ hs, float* __restrict__ out_lx)
{
    int idx = blockIdx.x*blockDim.x + threadIdx.x;   // B*C = 4096
    int b = idx >> 11, c = idx & 2047;
    out_lx[idx] = hs[((size_t)b*TT + (TT-1))*CC + c];
}

// =====================================================================
extern "C" void kernel_launch(void* const* d_in, const int* in_sizes, int n_in,
                              void* d_out, int out_size)
{
    (void)in_sizes; (void)n_in; (void)out_size;
    const float* hs     = (const float*)d_in[0];
    const float* shift  = (const float*)d_in[1];
    const float* wkv0   = (const float*)d_in[2];
    const float* maa_x  = (const float*)d_in[3];
    const float* maa_w  = (const float*)d_in[4];
    const float* maa_k  = (const float*)d_in[5];
    const float* maa_v  = (const float*)d_in[6];
    const float* maa_r  = (const float*)d_in[7];
    const float* maa_g  = (const float*)d_in[8];
    const float* w1     = (const float*)d_in[9];
    const float* w2     = (const float*)d_in[10];
    const float* tdecay = (const float*)d_in[11];
    const float* dw1    = (const float*)d_in[12];
    const float* dw2    = (const float*)d_in[13];
    const float* faaaa  = (const float*)d_in[14];
    const float* Wr     = (const float*)d_in[15];
    const float* Wk     = (const float*)d_in[16];
    const float* Wv     = (const float*)d_in[17];
    const float* Wg     = (const float*)d_in[18];
    const float* Wo     = (const float*)d_in[19];
    float* out = (float*)d_out;

    const size_t OFF_LX = (size_t)BQ*TT*CC;        // 16777216
    const size_t OFF_SF = OFF_LX + (size_t)BQ*CC;  // +4096

    cudaFuncSetAttribute(k2_proj,  cudaFuncAttributeMaxDynamicSharedMemorySize, K2_SMEM_BYTES);
    cudaFuncSetAttribute(k5_intra, cudaFuncAttributeMaxDynamicSharedMemorySize, K5_SMEM_BYTES);
    cudaFuncSetAttribute(k6_out,   cudaFuncAttributeMaxDynamicSharedMemorySize, K6_SMEM_BYTES);

    k1_mix <<<128, 256>>>(hs, shift, maa_x, w1);
    k2_proj<<<128, 256, K2_SMEM_BYTES>>>(hs, shift, maa_w, maa_k, maa_v, maa_r,
                                         maa_g, w2, dw1, Wk, Wv, Wr, Wg, dw2, tdecay);
    k3_chunk<<<BQ*NCH, 256>>>();
    k4_scan <<<32, 256>>>(wkv0, out + OFF_SF);
    k5_intra<<<BQ*NCH, 256, K5_SMEM_BYTES>>>(faaaa);
    k6_out  <<<dim3(MTOK/128, CC/128), 256, K6_SMEM_BYTES>>>(Wo, out);   // smem bytes FIXED
    k7_lx   <<<8, 512>>>(hs, out + OFF_LX);
}

// round 6
// speedup vs baseline: 2.0037x; 1.1233x over previous
#include <cuda_runtime.h>
#include <math.h>

// Problem constants
#define BQ   2
#define TT   4096
#define CC   2048
#define DD   64
#define MTOK (BQ*TT)      // 8192 tokens
#define LCH  32
#define NCH  (TT/LCH)     // 128 chunks per batch

// ---------------- device scratch ----------------
__device__ __align__(16) float g_y [MTOK*160];       // tanh mix features (tf32-rounded)
__device__ __align__(16) float g_A [5u*MTOK*CC];     // A_f tiles (tf32-rounded), 335MB
__device__ __align__(16) float g_t [MTOK*DD];        // tanh(decay proj) (tf32-rounded)
__device__ __align__(16) float g_r [MTOK*DD];
__device__ __align__(16) float g_k [MTOK*DD];
__device__ __align__(16) float g_v [MTOK*DD];
__device__ __align__(16) float g_gv[MTOK*DD];
__device__ __align__(16) float g_w [MTOK*DD];
__device__ __align__(16) float g_M [BQ*NCH*DD*DD];
__device__ __align__(16) float g_S [BQ*NCH*DD*DD];
__device__ __align__(16) float g_P [BQ*NCH*DD];
__device__ __align__(16) float g_o [MTOK*DD];

// ---------------- tf32 mma helpers ----------------
__device__ __forceinline__ float tf32r(float x) {
    unsigned u;
    asm("cvt.rna.tf32.f32 %0, %1;" : "=r"(u) : "f"(x));
    return __uint_as_float(u);
}
__device__ __forceinline__ void mma8(float* d,
    unsigned a0, unsigned a1, unsigned a2, unsigned a3,
    unsigned b0, unsigned b1)
{
    asm volatile(
        "mma.sync.aligned.m16n8k8.row.col.f32.tf32.tf32.f32 "
        "{%0,%1,%2,%3}, {%4,%5,%6,%7}, {%8,%9}, {%0,%1,%2,%3};"
        : "+f"(d[0]), "+f"(d[1]), "+f"(d[2]), "+f"(d[3])
        : "r"(a0), "r"(a1), "r"(a2), "r"(a3), "r"(b0), "r"(b1));
}
#define FB(x) __float_as_uint(x)

// =====================================================================
// K1 (proven): y = tanh( (hs + xx*maa_x) @ w1 ), tf32 mma
// =====================================================================
__global__ __launch_bounds__(256,1) void k1_mix(
    const float* __restrict__ hs, const float* __restrict__ shift,
    const float* __restrict__ maa_x, const float* __restrict__ w1)
{
    __shared__ float x_s [64*36];
    __shared__ float w1_s[32*168];
    const int tid  = threadIdx.x;
    const int lane = tid & 31, wid = tid >> 5;
    const int gi   = lane >> 2, t = lane & 3;
    const int m0   = blockIdx.x * 64;
    const int mt   = wid & 3;
    const int nbase= (wid >> 2) * 80;

    float acc[10][4];
    #pragma unroll
    for (int j = 0; j < 10; j++)
        #pragma unroll
        for (int e = 0; e < 4; e++) acc[j][e] = 0.f;

    for (int k0 = 0; k0 < CC; k0 += 32) {
        for (int idx = tid; idx < 2048; idx += 256) {
            int i = idx >> 5, kk = idx & 31;
            int m = m0 + i, c = k0 + kk;
            float cur  = hs[(size_t)m*CC + c];
            float prev = ((m & (TT-1)) == 0) ? shift[(m>>12)*CC + c]
                                             : hs[(size_t)(m-1)*CC + c];
            x_s[i*36 + kk] = tf32r(cur + (prev - cur) * __ldg(&maa_x[c]));
        }
        for (int idx = tid; idx < 5120; idx += 256) {
            int kk = idx / 160, n = idx - kk*160;
            w1_s[kk*168 + n] = tf32r(w1[(size_t)(k0+kk)*160 + n]);
        }
        __syncthreads();
        #pragma unroll
        for (int ks = 0; ks < 4; ks++) {
            const float* Ab = x_s + (mt*16)*36 + ks*8;
            unsigned a0 = FB(Ab[gi*36 + t]);
            unsigned a1 = FB(Ab[(gi+8)*36 + t]);
            unsigned a2 = FB(Ab[gi*36 + t + 4]);
            unsigned a3 = FB(Ab[(gi+8)*36 + t + 4]);
            #pragma unroll
            for (int j = 0; j < 10; j++) {
                int n0 = nbase + j*8;
                unsigned b0 = FB(w1_s[(ks*8+t)*168 + n0 + gi]);
                unsigned b1 = FB(w1_s[(ks*8+t+4)*168 + n0 + gi]);
                mma8(acc[j], a0,a1,a2,a3, b0,b1);
            }
        }
        __syncthreads();
    }
    const int mrow = m0 + mt*16 + gi;
    #pragma unroll
    for (int j = 0; j < 10; j++) {
        int n = nbase + j*8 + t*2;
        g_y[(size_t)mrow*160 + n]       = tf32r(tanhf(acc[j][0]));
        g_y[(size_t)mrow*160 + n + 1]   = tf32r(tanhf(acc[j][1]));
        g_y[(size_t)(mrow+8)*160 + n]   = tf32r(tanhf(acc[j][2]));
        g_y[(size_t)(mrow+8)*160 + n+1] = tf32r(tanhf(acc[j][3]));
    }
}

// =====================================================================
// K1b (new): per (m-tile 128, c-tile 64): for each f:
//   m_f = y_f @ w2_f (tf32 mma, K=32), then
//   A_f = hs + xx*(maa_f + m_f), tf32-rounded, stored to g_A.
// smem 27.6 KB -> 8 blocks/SM.
// =====================================================================
__global__ __launch_bounds__(256) void k1b_abuild(
    const float* __restrict__ hs, const float* __restrict__ shift,
    const float* __restrict__ maa_w, const float* __restrict__ maa_k,
    const float* __restrict__ maa_v, const float* __restrict__ maa_r,
    const float* __restrict__ maa_g, const float* __restrict__ w2)
{
    __shared__ float y_s [128*36];   // [i][kk]
    __shared__ float w2_s[32*72];    // [d][n]
    const int tid  = threadIdx.x;
    const int lane = tid & 31, wid = tid >> 5;   // wid 0..7 -> 16-row tile
    const int gi   = lane >> 2, t = lane & 3;
    const int m0   = blockIdx.x * 128;
    const int c0   = blockIdx.y * 64;

    #pragma unroll
    for (int f = 0; f < 5; f++) {
        __syncthreads();   // previous f's mma reads done before overwrite
        for (int idx = tid; idx < 128*32; idx += 256) {
            int i = idx >> 5, kk = idx & 31;
            y_s[i*36 + kk] = g_y[(size_t)(m0+i)*160 + f*32 + kk];
        }
        for (int idx = tid; idx < 2048; idx += 256) {
            int d = idx >> 6, n = idx & 63;
            w2_s[d*72 + n] = tf32r(w2[(size_t)(f*32 + d)*CC + c0 + n]);
        }
        __syncthreads();

        float acc[8][4];
        #pragma unroll
        for (int j = 0; j < 8; j++)
            #pragma unroll
            for (int e = 0; e < 4; e++) acc[j][e] = 0.f;

        #pragma unroll
        for (int ks = 0; ks < 4; ks++) {
            const float* Ab = y_s + (wid*16)*36 + ks*8;
            unsigned a0 = FB(Ab[gi*36 + t]);
            unsigned a1 = FB(Ab[(gi+8)*36 + t]);
            unsigned a2 = FB(Ab[gi*36 + t + 4]);
            unsigned a3 = FB(Ab[(gi+8)*36 + t + 4]);
            #pragma unroll
            for (int j = 0; j < 8; j++) {
                unsigned b0 = FB(w2_s[(ks*8+t)*72 + j*8 + gi]);
                unsigned b1 = FB(w2_s[(ks*8+t+4)*72 + j*8 + gi]);
                mma8(acc[j], a0,a1,a2,a3, b0,b1);
            }
        }

        const float* mp = (f==0) ? maa_w : (f==1) ? maa_k : (f==2) ? maa_v
                         : (f==3) ? maa_r : maa_g;
        #pragma unroll
        for (int j = 0; j < 8; j++) {
            #pragma unroll
            for (int e = 0; e < 4; e++) {
                int m  = m0 + wid*16 + gi + ((e & 2) ? 8 : 0);
                int cn = c0 + j*8 + t*2 + (e & 1);
                float cur  = hs[(size_t)m*CC + cn];
                float prev = ((m & (TT-1)) == 0) ? shift[(m>>12)*CC + cn]
                                                 : hs[(size_t)(m-1)*CC + cn];
                float a = cur + (prev - cur) * (__ldg(&mp[cn]) + acc[j][e]);
                g_A[((size_t)f*MTOK + m)*CC + cn] = tf32r(a);
            }
        }
    }
}

// =====================================================================
// K2' (new): out_f = A_f @ W_f,  M=8192 K=2048 N=64, grid (64 m-tiles, 5 f)
// Fused activation epilogue per f. smem 27.6 KB.
// =====================================================================
__global__ __launch_bounds__(256) void k2_gemm(
    const float* __restrict__ dw1, const float* __restrict__ Wk,
    const float* __restrict__ Wv,  const float* __restrict__ Wr,
    const float* __restrict__ Wg)
{
    __shared__ float a_s[128*36];   // [i][kk]
    __shared__ float w_s[32*72];    // [kk][n]
    const int tid  = threadIdx.x;
    const int lane = tid & 31, wid = tid >> 5;
    const int gi   = lane >> 2, t = lane & 3;
    const int m0   = blockIdx.x * 128;
    const int f    = blockIdx.y;
    const float* Wf = (f==0) ? dw1 : (f==1) ? Wk : (f==2) ? Wv
                     : (f==3) ? Wr : Wg;
    const float* Af = g_A + (size_t)f*MTOK*CC;

    float acc[8][4];
    #pragma unroll
    for (int j = 0; j < 8; j++)
        #pragma unroll
        for (int e = 0; e < 4; e++) acc[j][e] = 0.f;

    for (int k0 = 0; k0 < CC; k0 += 32) {
        for (int idx = tid; idx < 4096; idx += 256) {
            int i = idx >> 5, kk = idx & 31;
            a_s[i*36 + kk] = Af[(size_t)(m0+i)*CC + k0 + kk];   // pre-rounded
        }
        for (int idx = tid; idx < 2048; idx += 256) {
            int kk = idx >> 6, n = idx & 63;
            w_s[kk*72 + n] = tf32r(Wf[(size_t)(k0+kk)*64 + n]);
        }
        __syncthreads();
        #pragma unroll
        for (int ks = 0; ks < 4; ks++) {
            const float* Ab = a_s + (wid*16)*36 + ks*8;
            unsigned a0 = FB(Ab[gi*36 + t]);
            unsigned a1 = FB(Ab[(gi+8)*36 + t]);
            unsigned a2 = FB(Ab[gi*36 + t + 4]);
            unsigned a3 = FB(Ab[(gi+8)*36 + t + 4]);
            #pragma unroll
            for (int j = 0; j < 8; j++) {
                unsigned b0 = FB(w_s[(ks*8+t)*72 + j*8 + gi]);
                unsigned b1 = FB(w_s[(ks*8+t+4)*72 + j*8 + gi]);
                mma8(acc[j], a0,a1,a2,a3, b0,b1);
            }
        }
        __syncthreads();
    }

    #pragma unroll
    for (int j = 0; j < 8; j++) {
        #pragma unroll
        for (int e = 0; e < 4; e++) {
            int m = m0 + wid*16 + gi + ((e & 2) ? 8 : 0);
            int n = j*8 + t*2 + (e & 1);
            size_t ad = (size_t)m*64 + n;
            float x = acc[j][e];
            if      (f == 1) g_k[ad] = x;
            else if (f == 2) g_v[ad] = x;
            else if (f == 3) g_r[ad] = x;
            else if (f == 4) g_gv[ad] = x / (1.f + expf(-x));
            else             g_t[ad] = tf32r(tanhf(x));
        }
    }
}

// =====================================================================
// K2b (new): g_w = -exp(tdecay + g_t @ dw2),  M=8192 K=64 N=64
// =====================================================================
#define K2B_SMEM_BYTES ((128*68 + 64*72)*4)
__global__ __launch_bounds__(256) void k2b_decay(
    const float* __restrict__ dw2, const float* __restrict__ tdecay)
{
    extern __shared__ float smb[];
    float* t_s   = smb;             // [128][68]
    float* dw2_s = t_s + 128*68;    // [64][72]
    const int tid  = threadIdx.x;
    const int lane = tid & 31, wid = tid >> 5;
    const int gi   = lane >> 2, t = lane & 3;
    const int m0   = blockIdx.x * 128;

    for (int idx = tid; idx < 8192; idx += 256) {
        int i = idx >> 6, d = idx & 63;
        t_s[i*68 + d] = g_t[(size_t)(m0+i)*64 + d];
    }
    for (int idx = tid; idx < 4096; idx += 256) {
        int d = idx >> 6, n = idx & 63;
        dw2_s[d*72 + n] = tf32r(dw2[idx]);
    }
    __syncthreads();

    float acc[8][4];
    #pragma unroll
    for (int j = 0; j < 8; j++)
        #pragma unroll
        for (int e = 0; e < 4; e++) acc[j][e] = 0.f;

    #pragma unroll
    for (int ks = 0; ks < 8; ks++) {
        const float* Ab = t_s + (wid*16)*68 + ks*8;
        unsigned a0 = FB(Ab[gi*68 + t]);
        unsigned a1 = FB(Ab[(gi+8)*68 + t]);
        unsigned a2 = FB(Ab[gi*68 + t + 4]);
        unsigned a3 = FB(Ab[(gi+8)*68 + t + 4]);
        #pragma unroll
        for (int j = 0; j < 8; j++) {
            unsigned b0 = FB(dw2_s[(ks*8+t)*72 + j*8 + gi]);
            unsigned b1 = FB(dw2_s[(ks*8+t+4)*72 + j*8 + gi]);
            mma8(acc[j], a0,a1,a2,a3, b0,b1);
        }
    }
    #pragma unroll
    for (int j = 0; j < 8; j++) {
        #pragma unroll
        for (int e = 0; e < 4; e++) {
            int m = m0 + wid*16 + gi + ((e & 2) ? 8 : 0);
            int n = j*8 + t*2 + (e & 1);
            g_w[(size_t)m*64 + n] = -expf(__ldg(&tdecay[n]) + acc[j][e]);
        }
    }
}

// =====================================================================
// K3 (proven)
// =====================================================================
__global__ __launch_bounds__(256,1) void k3_chunk()
{
    __shared__ float k_s[32*64], v_s[32*64], cum_s[32*64], kh_s[32*64];
    const int bc   = blockIdx.x;
    const int tok0 = bc * 32;
    const int tid  = threadIdx.x;

    for (int idx = tid; idx < 2048; idx += 256) {
        size_t g = (size_t)tok0*64 + idx;
        k_s[idx]   = g_k[g];
        v_s[idx]   = g_v[g];
        cum_s[idx] = g_w[g];
    }
    __syncthreads();
    if (tid < 64) {
        float c = 0.f;
        for (int i = 0; i < 32; i++) { c += cum_s[i*64 + tid]; cum_s[i*64 + tid] = c; }
        g_P[bc*64 + tid] = expf(c);
        for (int i = 0; i < 32; i++)
            kh_s[i*64 + tid] = k_s[i*64 + tid] * expf(c - cum_s[i*64 + tid]);
    }
    __syncthreads();
    for (int it = 0; it < 16; it++) {
        int e  = tid + 256*it;
        int dk = e >> 6, dv = e & 63;
        float s = 0.f;
        #pragma unroll
        for (int i = 0; i < 32; i++)
            s += kh_s[i*64 + dk] * v_s[i*64 + dv];
        g_M[(size_t)bc*4096 + e] = s;
    }
}

// =====================================================================
// K4: inter-chunk scan, prefetch depth 32
// =====================================================================
__global__ __launch_bounds__(256,1) void k4_scan(
    const float* __restrict__ wkv0, float* __restrict__ out_sf)
{
    const int e  = blockIdx.x*256 + threadIdx.x;     // 0..8191
    const int b  = e >> 12, eb = e & 4095, dk = eb >> 6;
    float sv = wkv0[e];
    const float* Mp = g_M + (size_t)b*NCH*4096 + eb;
    const float* Pp = g_P + b*NCH*64 + dk;
    float*       Sp = g_S + (size_t)b*NCH*4096 + eb;

    float mq[32], pq[32];
    #pragma unroll
    for (int q = 0; q < 32; q++) { mq[q] = Mp[(size_t)q*4096]; pq[q] = Pp[q*64]; }

    for (int c = 0; c < NCH; c += 32) {
        #pragma unroll
        for (int q = 0; q < 32; q++) {
            Sp[(size_t)(c+q)*4096] = sv;
            sv = sv*pq[q] + mq[q];
            int cn = c + q + 32;
            if (cn < NCH) { mq[q] = Mp[(size_t)cn*4096]; pq[q] = Pp[cn*64]; }
        }
    }
    out_sf[e] = sv;
}

// =====================================================================
// K5 (proven)
// =====================================================================
#define K5_SMEM_FLOATS (4*(32*65) + 64*65 + 32*33 + 32)
#define K5_SMEM_BYTES  (K5_SMEM_FLOATS*4)

__global__ __launch_bounds__(256,1) void k5_intra(const float* __restrict__ faaaa)
{
    extern __shared__ float sm5[];
    float* r_s    = sm5;
    float* k_s    = r_s   + 32*65;
    float* v_s    = k_s   + 32*65;
    float* cum_s  = v_s   + 32*65;
    float* S_s    = cum_s + 32*65;
    float* sc_s   = S_s   + 64*65;
    float* diag_s = sc_s  + 32*33;

    const int bc   = blockIdx.x;
    const int tok0 = bc * 32;
    const int tid  = threadIdx.x;

    for (int idx = tid; idx < 2048; idx += 256) {
        int i = idx >> 6, d = idx & 63;
        size_t g = (size_t)tok0*64 + idx;
        r_s[i*65 + d]   = g_r[g];
        k_s[i*65 + d]   = g_k[g];
        v_s[i*65 + d]   = g_v[g];
        cum_s[i*65 + d] = g_w[g];
    }
    for (int idx = tid; idx < 4096; idx += 256) {
        int dk = idx >> 6, dv = idx & 63;
        S_s[dk*65 + dv] = g_S[(size_t)bc*4096 + idx];
    }
    __syncthreads();
    if (tid < 64) {
        float c = 0.f;
        for (int i = 0; i < 32; i++) { c += cum_s[i*65 + tid]; cum_s[i*65 + tid] = c; }
    }
    __syncthreads();
    if (tid < 32) {
        float s = 0.f;
        #pragma unroll
        for (int d = 0; d < 64; d++)
            s += r_s[tid*65 + d] * __ldg(&faaaa[d]) * k_s[tid*65 + d];
        diag_s[tid] = s;
    }
    __syncthreads();
    for (int idx = tid; idx < 2048; idx += 256) {
        int i = idx >> 6, d = idx & 63;
        float ce = (i == 0) ? 0.f : cum_s[(i-1)*65 + d];
        r_s[i*65 + d] *= expf(ce);
        k_s[i*65 + d] *= expf(-cum_s[i*65 + d]);
    }
    __syncthreads();
    #pragma unroll
    for (int q = 0; q < 4; q++) {
        int idx = tid + 256*q;
        int i = idx >> 5, j = idx & 31;
        float val;
        if (j < i) {
            float s = 0.f;
            #pragma unroll
            for (int d = 0; d < 64; d++)
                s += r_s[i*65 + d] * k_s[j*65 + d];
            val = s;
        } else {
            val = (j == i) ? diag_s[i] : 0.f;
        }
        sc_s[i*33 + j] = val;
    }
    __syncthreads();
    #pragma unroll
    for (int q = 0; q < 8; q++) {
        int idx = tid + 256*q;
        int i = idx >> 6, dv = idx & 63;
        float o = 0.f;
        #pragma unroll
        for (int j = 0; j < 32; j++)
            o += sc_s[i*33 + j] * v_s[j*65 + dv];
        #pragma unroll
        for (int d = 0; d < 64; d++)
            o += r_s[i*65 + d] * S_s[d*65 + dv];
        g_o[(size_t)tok0*64 + idx] = o;
    }
}

// =====================================================================
// K6 (proven): out = (o * g) @ W_o via tf32 mma, 128x128 tile
// =====================================================================
#define K6_SMEM_BYTES ((128*68 + 64*136)*4)
__global__ __launch_bounds__(256,1) void k6_out(
    const float* __restrict__ Wo, float* __restrict__ out)
{
    extern __shared__ float sm6[];
    float* a_s = sm6;
    float* b_s = a_s + 128*68;

    const int tid  = threadIdx.x;
    const int lane = tid & 31, wid = tid >> 5;
    const int gi   = lane >> 2, t = lane & 3;
    const int bm = blockIdx.x * 128, bn = blockIdx.y * 128;

    for (int idx = tid; idx < 8192; idx += 256) {
        int i = idx >> 6, d = idx & 63;
        size_t g = (size_t)(bm+i)*64 + d;
        a_s[i*68 + d] = tf32r(g_o[g] * g_gv[g]);
    }
    for (int idx = tid; idx < 8192; idx += 256) {
        int dd = idx >> 7, n = idx & 127;
        b_s[dd*136 + n] = tf32r(Wo[(size_t)dd*CC + bn + n]);
    }
    __syncthreads();

    const int rb = (wid & 3) * 32;
    const int n0 = (wid >> 2) * 64;
    float acc[2][8][4];
    #pragma unroll
    for (int mi = 0; mi < 2; mi++)
        #pragma unroll
        for (int j = 0; j < 8; j++)
            #pragma unroll
            for (int e = 0; e < 4; e++) acc[mi][j][e] = 0.f;

    #pragma unroll
    for (int ks = 0; ks < 8; ks++) {
        unsigned a[2][4];
        #pragma unroll
        for (int mi = 0; mi < 2; mi++) {
            const float* Ab = a_s + (rb + mi*16)*68 + ks*8;
            a[mi][0] = FB(Ab[gi*68 + t]);
            a[mi][1] = FB(Ab[(gi+8)*68 + t]);
            a[mi][2] = FB(Ab[gi*68 + t + 4]);
            a[mi][3] = FB(Ab[(gi+8)*68 + t + 4]);
        }
        #pragma unroll
        for (int j = 0; j < 8; j++) {
            unsigned b0 = FB(b_s[(ks*8+t)*136 + n0 + j*8 + gi]);
            unsigned b1 = FB(b_s[(ks*8+t+4)*136 + n0 + j*8 + gi]);
            mma8(acc[0][j], a[0][0],a[0][1],a[0][2],a[0][3], b0,b1);
            mma8(acc[1][j], a[1][0],a[1][1],a[1][2],a[1][3], b0,b1);
        }
    }
    #pragma unroll
    for (int mi = 0; mi < 2; mi++)
        #pragma unroll
        for (int j = 0; j < 8; j++) {
            int m = bm + rb + mi*16 + gi;
            int n = bn + n0 + j*8 + t*2;
            out[(size_t)m*CC + n]       = acc[mi][j][0];
            out[(size_t)m*CC + n + 1]   = acc[mi][j][1];
            out[(size_t)(m+8)*CC + n]   = acc[mi][j][2];
            out[(size_t)(m+8)*CC + n+1] = acc[mi][j][3];
        }
}

// lx = hs[:, -1, :]
__global__ void k7_lx(const float* __restrict__ hs, float* __restrict__ out_lx)
{
    int idx = blockIdx.x*blockDim.x + threadIdx.x;
    int b = idx >> 11, c = idx & 2047;
    out_lx[idx] = hs[((size_t)b*TT + (TT-1))*CC + c];
}

// =====================================================================
extern "C" void kernel_launch(void* const* d_in, const int* in_sizes, int n_in,
                              void* d_out, int out_size)
{
    (void)in_sizes; (void)n_in; (void)out_size;
    const float* hs     = (const float*)d_in[0];
    const float* shift  = (const float*)d_in[1];
    const float* wkv0   = (const float*)d_in[2];
    const float* maa_x  = (const float*)d_in[3];
    const float* maa_w  = (const float*)d_in[4];
    const float* maa_k  = (const float*)d_in[5];
    const float* maa_v  = (const float*)d_in[6];
    const float* maa_r  = (const float*)d_in[7];
    const float* maa_g  = (const float*)d_in[8];
    const float* w1     = (const float*)d_in[9];
    const float* w2     = (const float*)d_in[10];
    const float* tdecay = (const float*)d_in[11];
    const float* dw1    = (const float*)d_in[12];
    const float* dw2    = (const float*)d_in[13];
    const float* faaaa  = (const float*)d_in[14];
    const float* Wr     = (const float*)d_in[15];
    const float* Wk     = (const float*)d_in[16];
    const float* Wv     = (const float*)d_in[17];
    const float* Wg     = (const float*)d_in[18];
    const float* Wo     = (const float*)d_in[19];
    float* out = (float*)d_out;

    const size_t OFF_LX = (size_t)BQ*TT*CC;
    const size_t OFF_SF = OFF_LX + (size_t)BQ*CC;

    cudaFuncSetAttribute(k2b_decay, cudaFuncAttributeMaxDynamicSharedMemorySize, K2B_SMEM_BYTES);
    cudaFuncSetAttribute(k5_intra,  cudaFuncAttributeMaxDynamicSharedMemorySize, K5_SMEM_BYTES);
    cudaFuncSetAttribute(k6_out,    cudaFuncAttributeMaxDynamicSharedMemorySize, K6_SMEM_BYTES);

    k1_mix    <<<128, 256>>>(hs, shift, maa_x, w1);
    k1b_abuild<<<dim3(MTOK/128, CC/64), 256>>>(hs, shift, maa_w, maa_k, maa_v,
                                               maa_r, maa_g, w2);
    k2_gemm   <<<dim3(MTOK/128, 5), 256>>>(dw1, Wk, Wv, Wr, Wg);
    k2b_decay <<<MTOK/128, 256, K2B_SMEM_BYTES>>>(dw2, tdecay);
    k3_chunk  <<<BQ*NCH, 256>>>();
    k4_scan   <<<32, 256>>>(wkv0, out + OFF_SF);
    k5_intra  <<<BQ*NCH, 256, K5_SMEM_BYTES>>>(faaaa);
    k6_out    <<<dim3(MTOK/128, CC/128), 256, K6_SMEM_BYTES>>>(Wo, out);
    k7_lx     <<<8, 512>>>(hs, out + OFF_LX);
}

// round 7
// speedup vs baseline: 2.7182x; 1.3566x over previous
#include <cuda_runtime.h>
#include <math.h>

// Problem constants
#define BQ   2
#define TT   4096
#define CC   2048
#define DD   64
#define MTOK (BQ*TT)      // 8192 tokens
#define LCH  32
#define NCH  (TT/LCH)     // 128 chunks per batch

// ---------------- device scratch ----------------
__device__ __align__(16) float g_y [MTOK*160];       // tanh mix features (tf32-rounded)
__device__ __align__(16) float g_A [5u*MTOK*CC];     // A_f tiles (tf32-rounded)
__device__ __align__(16) float g_t [MTOK*DD];        // tanh(decay proj)
__device__ __align__(16) float g_r [MTOK*DD];
__device__ __align__(16) float g_k [MTOK*DD];
__device__ __align__(16) float g_v [MTOK*DD];
__device__ __align__(16) float g_gv[MTOK*DD];
__device__ __align__(16) float g_w [MTOK*DD];
__device__ __align__(16) float g_M [BQ*NCH*DD*DD];
__device__ __align__(16) float g_S [BQ*NCH*DD*DD];
__device__ __align__(16) float g_P [BQ*NCH*DD];
__device__ __align__(16) float g_o [MTOK*DD];

// ---------------- tf32 mma helpers ----------------
__device__ __forceinline__ float tf32r(float x) {
    unsigned u;
    asm("cvt.rna.tf32.f32 %0, %1;" : "=r"(u) : "f"(x));
    return __uint_as_float(u);
}
__device__ __forceinline__ void mma8(float* d,
    unsigned a0, unsigned a1, unsigned a2, unsigned a3,
    unsigned b0, unsigned b1)
{
    asm volatile(
        "mma.sync.aligned.m16n8k8.row.col.f32.tf32.tf32.f32 "
        "{%0,%1,%2,%3}, {%4,%5,%6,%7}, {%8,%9}, {%0,%1,%2,%3};"
        : "+f"(d[0]), "+f"(d[1]), "+f"(d[2]), "+f"(d[3])
        : "r"(a0), "r"(a1), "r"(a2), "r"(a3), "r"(b0), "r"(b1));
}
#define FB(x) __float_as_uint(x)

// =====================================================================
// K1 v2: y = tanh( (hs + xx*maa_x) @ w1 ), BM=32, reg-prefetch pipeline
// grid 256 blocks, 8 warps: (mt 0..1 rows, ng 0..3 col-groups of 40)
// =====================================================================
__global__ __launch_bounds__(256) void k1_mix(
    const float* __restrict__ hs, const float* __restrict__ shift,
    const float* __restrict__ maa_x, const float* __restrict__ w1)
{
    __shared__ float x_s [32*36];
    __shared__ float w1_s[32*168];
    const int tid  = threadIdx.x;
    const int lane = tid & 31, wid = tid >> 5;
    const int gi   = lane >> 2, t = lane & 3;
    const int m0   = blockIdx.x * 32;
    const int mt   = wid & 1;
    const int ng   = wid >> 1;

    float acc[5][4];
    #pragma unroll
    for (int j = 0; j < 5; j++)
        #pragma unroll
        for (int e = 0; e < 4; e++) acc[j][e] = 0.f;

    float px[4], pw[20];
    #pragma unroll
    for (int u = 0; u < 4; u++) {
        int idx = tid + 256*u, i = idx >> 5, kk = idx & 31;
        int m = m0 + i, c = kk;
        float cur  = hs[(size_t)m*CC + c];
        float prev = ((m & (TT-1)) == 0) ? shift[(m>>12)*CC + c]
                                         : hs[(size_t)(m-1)*CC + c];
        px[u] = tf32r(cur + (prev - cur) * __ldg(&maa_x[c]));
    }
    #pragma unroll
    for (int u = 0; u < 20; u++) {
        int idx = tid + 256*u, kk = idx/160, n = idx - kk*160;
        pw[u] = tf32r(w1[(size_t)kk*160 + n]);
    }

    for (int k0 = 0; k0 < CC; k0 += 32) {
        __syncthreads();
        #pragma unroll
        for (int u = 0; u < 4; u++) {
            int idx = tid + 256*u;
            x_s[(idx >> 5)*36 + (idx & 31)] = px[u];
        }
        #pragma unroll
        for (int u = 0; u < 20; u++) {
            int idx = tid + 256*u, kk = idx/160, n = idx - kk*160;
            w1_s[kk*168 + n] = pw[u];
        }
        __syncthreads();
        const int kn = k0 + 32;
        if (kn < CC) {
            #pragma unroll
            for (int u = 0; u < 4; u++) {
                int idx = tid + 256*u, i = idx >> 5, kk = idx & 31;
                int m = m0 + i, c = kn + kk;
                float cur  = hs[(size_t)m*CC + c];
                float prev = ((m & (TT-1)) == 0) ? shift[(m>>12)*CC + c]
                                                 : hs[(size_t)(m-1)*CC + c];
                px[u] = tf32r(cur + (prev - cur) * __ldg(&maa_x[c]));
            }
            #pragma unroll
            for (int u = 0; u < 20; u++) {
                int idx = tid + 256*u, kk = idx/160, n = idx - kk*160;
                pw[u] = tf32r(w1[(size_t)(kn+kk)*160 + n]);
            }
        }
        #pragma unroll
        for (int ks = 0; ks < 4; ks++) {
            const float* Ab = x_s + (mt*16)*36 + ks*8;
            unsigned a0 = FB(Ab[gi*36 + t]);
            unsigned a1 = FB(Ab[(gi+8)*36 + t]);
            unsigned a2 = FB(Ab[gi*36 + t + 4]);
            unsigned a3 = FB(Ab[(gi+8)*36 + t + 4]);
            #pragma unroll
            for (int j = 0; j < 5; j++) {
                int n0 = ng*40 + j*8;
                unsigned b0 = FB(w1_s[(ks*8+t)*168 + n0 + gi]);
                unsigned b1 = FB(w1_s[(ks*8+t+4)*168 + n0 + gi]);
                mma8(acc[j], a0,a1,a2,a3, b0,b1);
            }
        }
    }
    const int mrow = m0 + mt*16 + gi;
    #pragma unroll
    for (int j = 0; j < 5; j++) {
        int n = ng*40 + j*8 + t*2;
        g_y[(size_t)mrow*160 + n]       = tf32r(tanhf(acc[j][0]));
        g_y[(size_t)mrow*160 + n + 1]   = tf32r(tanhf(acc[j][1]));
        g_y[(size_t)(mrow+8)*160 + n]   = tf32r(tanhf(acc[j][2]));
        g_y[(size_t)(mrow+8)*160 + n+1] = tf32r(tanhf(acc[j][3]));
    }
}

// =====================================================================
// K1b v2: A_f = hs + xx*(maa_f + y_f@w2_f), fully smem-staged.
// Block: 64 tokens x 64 cols. hs tile (65 rows incl. prev) loaded
// coalesced once; g_A written via staging buffer in 256B rows.
// grid (128, 32), 43.8KB static smem -> ~5 blocks/SM.
// =====================================================================
__global__ __launch_bounds__(256) void k1b_abuild(
    const float* __restrict__ hs, const float* __restrict__ shift,
    const float* __restrict__ maa_w, const float* __restrict__ maa_k,
    const float* __restrict__ maa_v, const float* __restrict__ maa_r,
    const float* __restrict__ maa_g, const float* __restrict__ w2)
{
    __shared__ float hs_s[65*68];    // row i <-> global row m0-1+i
    __shared__ float w2_s[32*68];    // [d][c]
    __shared__ float st_s[64*68];    // A staging
    __shared__ float maa_s[64];
    const int tid  = threadIdx.x;
    const int lane = tid & 31, wid = tid >> 5;
    const int gi   = lane >> 2, t = lane & 3;
    const int m0   = blockIdx.x * 64;
    const int c0   = blockIdx.y * 64;
    const int mt   = wid & 3;          // 16-row tile
    const int nh   = (wid >> 2) * 32;  // 32-col half

    // hs tile: rows m0-1 .. m0+63 (coalesced, 256B per row)
    for (int idx = tid; idx < 65*64; idx += 256) {
        int i = idx >> 6, c = idx & 63;
        float v;
        if (i == 0 && (m0 & (TT-1)) == 0)
            v = shift[(m0 >> 12)*CC + c0 + c];
        else
            v = hs[(size_t)(m0 - 1 + i)*CC + c0 + c];
        hs_s[i*68 + c] = v;
    }

    #pragma unroll
    for (int f = 0; f < 5; f++) {
        __syncthreads();   // hs ready (f=0) / prev-f w2 reads + st_s copyout done
        for (int idx = tid; idx < 2048; idx += 256) {
            int d = idx >> 6, c = idx & 63;
            w2_s[d*68 + c] = tf32r(w2[(size_t)(f*32 + d)*CC + c0 + c]);
        }
        if (tid < 64) {
            const float* mp = (f==0) ? maa_w : (f==1) ? maa_k : (f==2) ? maa_v
                             : (f==3) ? maa_r : maa_g;
            maa_s[tid] = mp[c0 + tid];
        }
        __syncthreads();

        float acc[4][4];
        #pragma unroll
        for (int j = 0; j < 4; j++)
            #pragma unroll
            for (int e = 0; e < 4; e++) acc[j][e] = 0.f;

        const size_t yb = (size_t)(m0 + mt*16)*160 + f*32;
        #pragma unroll
        for (int ks = 0; ks < 4; ks++) {
            unsigned a0 = FB(g_y[yb + (size_t)gi*160     + ks*8 + t]);
            unsigned a1 = FB(g_y[yb + (size_t)(gi+8)*160 + ks*8 + t]);
            unsigned a2 = FB(g_y[yb + (size_t)gi*160     + ks*8 + t + 4]);
            unsigned a3 = FB(g_y[yb + (size_t)(gi+8)*160 + ks*8 + t + 4]);
            #pragma unroll
            for (int j = 0; j < 4; j++) {
                unsigned b0 = FB(w2_s[(ks*8+t)*68   + nh + j*8 + gi]);
                unsigned b1 = FB(w2_s[(ks*8+t+4)*68 + nh + j*8 + gi]);
                mma8(acc[j], a0,a1,a2,a3, b0,b1);
            }
        }

        // A build from smem -> staging (all smem, no scattered global)
        #pragma unroll
        for (int j = 0; j < 4; j++) {
            #pragma unroll
            for (int e = 0; e < 4; e++) {
                int r = mt*16 + gi + ((e & 2) ? 8 : 0);
                int c = nh + j*8 + t*2 + (e & 1);
                float cur  = hs_s[(r+1)*68 + c];
                float prev = hs_s[r*68 + c];
                float a = cur + (prev - cur)*(maa_s[c] + acc[j][e]);
                st_s[r*68 + c] = tf32r(a);
            }
        }
        __syncthreads();

        // coalesced copy-out (256B rows)
        for (int idx = tid; idx < 4096; idx += 256) {
            int r = idx >> 6, c = idx & 63;
            g_A[((size_t)f*MTOK + m0 + r)*CC + c0 + c] = st_s[r*68 + c];
        }
    }
}

// =====================================================================
// K2' v2: out_f = A_f @ W_f, reg double-buffered. grid (64, 5).
// =====================================================================
__global__ __launch_bounds__(256) void k2_gemm(
    const float* __restrict__ dw1, const float* __restrict__ Wk,
    const float* __restrict__ Wv,  const float* __restrict__ Wr,
    const float* __restrict__ Wg)
{
    __shared__ float a_s[128*36];
    __shared__ float w_s[32*72];
    const int tid  = threadIdx.x;
    const int lane = tid & 31, wid = tid >> 5;
    const int gi   = lane >> 2, t = lane & 3;
    const int m0   = blockIdx.x * 128;
    const int f    = blockIdx.y;
    const float* Wf = (f==0) ? dw1 : (f==1) ? Wk : (f==2) ? Wv
                     : (f==3) ? Wr : Wg;
    const float* Af = g_A + (size_t)f*MTOK*CC;

    float acc[8][4];
    #pragma unroll
    for (int j = 0; j < 8; j++)
        #pragma unroll
        for (int e = 0; e < 4; e++) acc[j][e] = 0.f;

    float pa[16], pw[8];
    #pragma unroll
    for (int u = 0; u < 16; u++) {
        int idx = tid + 256*u, i = idx >> 5, kk = idx & 31;
        pa[u] = Af[(size_t)(m0+i)*CC + kk];
    }
    #pragma unroll
    for (int u = 0; u < 8; u++) {
        int idx = tid + 256*u, kk = idx >> 6, n = idx & 63;
        pw[u] = tf32r(Wf[(size_t)kk*64 + n]);
    }

    for (int k0 = 0; k0 < CC; k0 += 32) {
        __syncthreads();
        #pragma unroll
        for (int u = 0; u < 16; u++) {
            int idx = tid + 256*u;
            a_s[(idx >> 5)*36 + (idx & 31)] = pa[u];
        }
        #pragma unroll
        for (int u = 0; u < 8; u++) {
            int idx = tid + 256*u;
            w_s[(idx >> 6)*72 + (idx & 63)] = pw[u];
        }
        __syncthreads();
        const int kn = k0 + 32;
        if (kn < CC) {
            #pragma unroll
            for (int u = 0; u < 16; u++) {
                int idx = tid + 256*u, i = idx >> 5, kk = idx & 31;
                pa[u] = Af[(size_t)(m0+i)*CC + kn + kk];
            }
            #pragma unroll
            for (int u = 0; u < 8; u++) {
                int idx = tid + 256*u, kk = idx >> 6, n = idx & 63;
                pw[u] = tf32r(Wf[(size_t)(kn+kk)*64 + n]);
            }
        }
        #pragma unroll
        for (int ks = 0; ks < 4; ks++) {
            const float* Ab = a_s + (wid*16)*36 + ks*8;
            unsigned a0 = FB(Ab[gi*36 + t]);
            unsigned a1 = FB(Ab[(gi+8)*36 + t]);
            unsigned a2 = FB(Ab[gi*36 + t + 4]);
            unsigned a3 = FB(Ab[(gi+8)*36 + t + 4]);
            #pragma unroll
            for (int j = 0; j < 8; j++) {
                unsigned b0 = FB(w_s[(ks*8+t)*72 + j*8 + gi]);
                unsigned b1 = FB(w_s[(ks*8+t+4)*72 + j*8 + gi]);
                mma8(acc[j], a0,a1,a2,a3, b0,b1);
            }
        }
    }

    #pragma unroll
    for (int j = 0; j < 8; j++) {
        #pragma unroll
        for (int e = 0; e < 4; e++) {
            int m = m0 + wid*16 + gi + ((e & 2) ? 8 : 0);
            int n = j*8 + t*2 + (e & 1);
            size_t ad = (size_t)m*64 + n;
            float x = acc[j][e];
            if      (f == 1) g_k[ad] = x;
            else if (f == 2) g_v[ad] = x;
            else if (f == 3) g_r[ad] = x;
            else if (f == 4) g_gv[ad] = x / (1.f + expf(-x));
            else             g_t[ad] = tf32r(tanhf(x));
        }
    }
}

// =====================================================================
// K2b (proven): g_w = -exp(tdecay + g_t @ dw2)
// =====================================================================
#define K2B_SMEM_BYTES ((128*68 + 64*72)*4)
__global__ __launch_bounds__(256) void k2b_decay(
    const float* __restrict__ dw2, const float* __restrict__ tdecay)
{
    extern __shared__ float smb[];
    float* t_s   = smb;
    float* dw2_s = t_s + 128*68;
    const int tid  = threadIdx.x;
    const int lane = tid & 31, wid = tid >> 5;
    const int gi   = lane >> 2, t = lane & 3;
    const int m0   = blockIdx.x * 128;

    for (int idx = tid; idx < 8192; idx += 256) {
        int i = idx >> 6, d = idx & 63;
        t_s[i*68 + d] = g_t[(size_t)(m0+i)*64 + d];
    }
    for (int idx = tid; idx < 4096; idx += 256) {
        int d = idx >> 6, n = idx & 63;
        dw2_s[d*72 + n] = tf32r(dw2[idx]);
    }
    __syncthreads();

    float acc[8][4];
    #pragma unroll
    for (int j = 0; j < 8; j++)
        #pragma unroll
        for (int e = 0; e < 4; e++) acc[j][e] = 0.f;

    #pragma unroll
    for (int ks = 0; ks < 8; ks++) {
        const float* Ab = t_s + (wid*16)*68 + ks*8;
        unsigned a0 = FB(Ab[gi*68 + t]);
        unsigned a1 = FB(Ab[(gi+8)*68 + t]);
        unsigned a2 = FB(Ab[gi*68 + t + 4]);
        unsigned a3 = FB(Ab[(gi+8)*68 + t + 4]);
        #pragma unroll
        for (int j = 0; j < 8; j++) {
            unsigned b0 = FB(dw2_s[(ks*8+t)*72 + j*8 + gi]);
            unsigned b1 = FB(dw2_s[(ks*8+t+4)*72 + j*8 + gi]);
            mma8(acc[j], a0,a1,a2,a3, b0,b1);
        }
    }
    #pragma unroll
    for (int j = 0; j < 8; j++) {
        #pragma unroll
        for (int e = 0; e < 4; e++) {
            int m = m0 + wid*16 + gi + ((e & 2) ? 8 : 0);
            int n = j*8 + t*2 + (e & 1);
            g_w[(size_t)m*64 + n] = -expf(__ldg(&tdecay[n]) + acc[j][e]);
        }
    }
}

// =====================================================================
// K3 (proven)
// =====================================================================
__global__ __launch_bounds__(256,1) void k3_chunk()
{
    __shared__ float k_s[32*64], v_s[32*64], cum_s[32*64], kh_s[32*64];
    const int bc   = blockIdx.x;
    const int tok0 = bc * 32;
    const int tid  = threadIdx.x;

    for (int idx = tid; idx < 2048; idx += 256) {
        size_t g = (size_t)tok0*64 + idx;
        k_s[idx]   = g_k[g];
        v_s[idx]   = g_v[g];
        cum_s[idx] = g_w[g];
    }
    __syncthreads();
    if (tid < 64) {
        float c = 0.f;
        for (int i = 0; i < 32; i++) { c += cum_s[i*64 + tid]; cum_s[i*64 + tid] = c; }
        g_P[bc*64 + tid] = expf(c);
        for (int i = 0; i < 32; i++)
            kh_s[i*64 + tid] = k_s[i*64 + tid] * expf(c - cum_s[i*64 + tid]);
    }
    __syncthreads();
    for (int it = 0; it < 16; it++) {
        int e  = tid + 256*it;
        int dk = e >> 6, dv = e & 63;
        float s = 0.f;
        #pragma unroll
        for (int i = 0; i < 32; i++)
            s += kh_s[i*64 + dk] * v_s[i*64 + dv];
        g_M[(size_t)bc*4096 + e] = s;
    }
}

// =====================================================================
// K4 (proven): inter-chunk scan, prefetch depth 32
// =====================================================================
__global__ __launch_bounds__(256,1) void k4_scan(
    const float* __restrict__ wkv0, float* __restrict__ out_sf)
{
    const int e  = blockIdx.x*256 + threadIdx.x;
    const int b  = e >> 12, eb = e & 4095, dk = eb >> 6;
    float sv = wkv0[e];
    const float* Mp = g_M + (size_t)b*NCH*4096 + eb;
    const float* Pp = g_P + b*NCH*64 + dk;
    float*       Sp = g_S + (size_t)b*NCH*4096 + eb;

    float mq[32], pq[32];
    #pragma unroll
    for (int q = 0; q < 32; q++) { mq[q] = Mp[(size_t)q*4096]; pq[q] = Pp[q*64]; }

    for (int c = 0; c < NCH; c += 32) {
        #pragma unroll
        for (int q = 0; q < 32; q++) {
            Sp[(size_t)(c+q)*4096] = sv;
            sv = sv*pq[q] + mq[q];
            int cn = c + q + 32;
            if (cn < NCH) { mq[q] = Mp[(size_t)cn*4096]; pq[q] = Pp[cn*64]; }
        }
    }
    out_sf[e] = sv;
}

// =====================================================================
// K5 (proven)
// =====================================================================
#define K5_SMEM_FLOATS (4*(32*65) + 64*65 + 32*33 + 32)
#define K5_SMEM_BYTES  (K5_SMEM_FLOATS*4)

__global__ __launch_bounds__(256,1) void k5_intra(const float* __restrict__ faaaa)
{
    extern __shared__ float sm5[];
    float* r_s    = sm5;
    float* k_s    = r_s   + 32*65;
    float* v_s    = k_s   + 32*65;
    float* cum_s  = v_s   + 32*65;
    float* S_s    = cum_s + 32*65;
    float* sc_s   = S_s   + 64*65;
    float* diag_s = sc_s  + 32*33;

    const int bc   = blockIdx.x;
    const int tok0 = bc * 32;
    const int tid  = threadIdx.x;

    for (int idx = tid; idx < 2048; idx += 256) {
        int i = idx >> 6, d = idx & 63;
        size_t g = (size_t)tok0*64 + idx;
        r_s[i*65 + d]   = g_r[g];
        k_s[i*65 + d]   = g_k[g];
        v_s[i*65 + d]   = g_v[g];
        cum_s[i*65 + d] = g_w[g];
    }
    for (int idx = tid; idx < 4096; idx += 256) {
        int dk = idx >> 6, dv = idx & 63;
        S_s[dk*65 + dv] = g_S[(size_t)bc*4096 + idx];
    }
    __syncthreads();
    if (tid < 64) {
        float c = 0.f;
        for (int i = 0; i < 32; i++) { c += cum_s[i*65 + tid]; cum_s[i*65 + tid] = c; }
    }
    __syncthreads();
    if (tid < 32) {
        float s = 0.f;
        #pragma unroll
        for (int d = 0; d < 64; d++)
            s += r_s[tid*65 + d] * __ldg(&faaaa[d]) * k_s[tid*65 + d];
        diag_s[tid] = s;
    }
    __syncthreads();
    for (int idx = tid; idx < 2048; idx += 256) {
        int i = idx >> 6, d = idx & 63;
        float ce = (i == 0) ? 0.f : cum_s[(i-1)*65 + d];
        r_s[i*65 + d] *= expf(ce);
        k_s[i*65 + d] *= expf(-cum_s[i*65 + d]);
    }
    __syncthreads();
    #pragma unroll
    for (int q = 0; q < 4; q++) {
        int idx = tid + 256*q;
        int i = idx >> 5, j = idx & 31;
        float val;
        if (j < i) {
            float s = 0.f;
            #pragma unroll
            for (int d = 0; d < 64; d++)
                s += r_s[i*65 + d] * k_s[j*65 + d];
            val = s;
        } else {
            val = (j == i) ? diag_s[i] : 0.f;
        }
        sc_s[i*33 + j] = val;
    }
    __syncthreads();
    #pragma unroll
    for (int q = 0; q < 8; q++) {
        int idx = tid + 256*q;
        int i = idx >> 6, dv = idx & 63;
        float o = 0.f;
        #pragma unroll
        for (int j = 0; j < 32; j++)
            o += sc_s[i*33 + j] * v_s[j*65 + dv];
        #pragma unroll
        for (int d = 0; d < 64; d++)
            o += r_s[i*65 + d] * S_s[d*65 + dv];
        g_o[(size_t)tok0*64 + idx] = o;
    }
}

// =====================================================================
// K6 (proven): out = (o * g) @ W_o via tf32 mma, 128x128 tile
// =====================================================================
#define K6_SMEM_BYTES ((128*68 + 64*136)*4)
__global__ __launch_bounds__(256,1) void k6_out(
    const float* __restrict__ Wo, float* __restrict__ out)
{
    extern __shared__ float sm6[];
    float* a_s = sm6;
    float* b_s = a_s + 128*68;

    const int tid  = threadIdx.x;
    const int lane = tid & 31, wid = tid >> 5;
    const int gi   = lane >> 2, t = lane & 3;
    const int bm = blockIdx.x * 128, bn = blockIdx.y * 128;

    for (int idx = tid; idx < 8192; idx += 256) {
        int i = idx >> 6, d = idx & 63;
        size_t g = (size_t)(bm+i)*64 + d;
        a_s[i*68 + d] = tf32r(g_o[g] * g_gv[g]);
    }
    for (int idx = tid; idx < 8192; idx += 256) {
        int dd = idx >> 7, n = idx & 127;
        b_s[dd*136 + n] = tf32r(Wo[(size_t)dd*CC + bn + n]);
    }
    __syncthreads();

    const int rb = (wid & 3) * 32;
    const int n0 = (wid >> 2) * 64;
    float acc[2][8][4];
    #pragma unroll
    for (int mi = 0; mi < 2; mi++)
        #pragma unroll
        for (int j = 0; j < 8; j++)
            #pragma unroll
            for (int e = 0; e < 4; e++) acc[mi][j][e] = 0.f;

    #pragma unroll
    for (int ks = 0; ks < 8; ks++) {
        unsigned a[2][4];
        #pragma unroll
        for (int mi = 0; mi < 2; mi++) {
            const float* Ab = a_s + (rb + mi*16)*68 + ks*8;
            a[mi][0] = FB(Ab[gi*68 + t]);
            a[mi][1] = FB(Ab[(gi+8)*68 + t]);
            a[mi][2] = FB(Ab[gi*68 + t + 4]);
            a[mi][3] = FB(Ab[(gi+8)*68 + t + 4]);
        }
        #pragma unroll
        for (int j = 0; j < 8; j++) {
            unsigned b0 = FB(b_s[(ks*8+t)*136 + n0 + j*8 + gi]);
            unsigned b1 = FB(b_s[(ks*8+t+4)*136 + n0 + j*8 + gi]);
            mma8(acc[0][j], a[0][0],a[0][1],a[0][2],a[0][3], b0,b1);
            mma8(acc[1][j], a[1][0],a[1][1],a[1][2],a[1][3], b0,b1);
        }
    }
    #pragma unroll
    for (int mi = 0; mi < 2; mi++)
        #pragma unroll
        for (int j = 0; j < 8; j++) {
            int m = bm + rb + mi*16 + gi;
            int n = bn + n0 + j*8 + t*2;
            out[(size_t)m*CC + n]       = acc[mi][j][0];
            out[(size_t)m*CC + n + 1]   = acc[mi][j][1];
            out[(size_t)(m+8)*CC + n]   = acc[mi][j][2];
            out[(size_t)(m+8)*CC + n+1] = acc[mi][j][3];
        }
}

// lx = hs[:, -1, :]
__global__ void k7_lx(const float* __restrict__ hs, float* __restrict__ out_lx)
{
    int idx = blockIdx.x*blockDim.x + threadIdx.x;
    int b = idx >> 11, c = idx & 2047;
    out_lx[idx] = hs[((size_t)b*TT + (TT-1))*CC + c];
}

// =====================================================================
extern "C" void kernel_launch(void* const* d_in, const int* in_sizes, int n_in,
                              void* d_out, int out_size)
{
    (void)in_sizes; (void)n_in; (void)out_size;
    const float* hs     = (const float*)d_in[0];
    const float* shift  = (const float*)d_in[1];
    const float* wkv0   = (const float*)d_in[2];
    const float* maa_x  = (const float*)d_in[3];
    const float* maa_w  = (const float*)d_in[4];
    const float* maa_k  = (const float*)d_in[5];
    const float* maa_v  = (const float*)d_in[6];
    const float* maa_r  = (const float*)d_in[7];
    const float* maa_g  = (const float*)d_in[8];
    const float* w1     = (const float*)d_in[9];
    const float* w2     = (const float*)d_in[10];
    const float* tdecay = (const float*)d_in[11];
    const float* dw1    = (const float*)d_in[12];
    const float* dw2    = (const float*)d_in[13];
    const float* faaaa  = (const float*)d_in[14];
    const float* Wr     = (const float*)d_in[15];
    const float* Wk     = (const float*)d_in[16];
    const float* Wv     = (const float*)d_in[17];
    const float* Wg     = (const float*)d_in[18];
    const float* Wo     = (const float*)d_in[19];
    float* out = (float*)d_out;

    const size_t OFF_LX = (size_t)BQ*TT*CC;
    const size_t OFF_SF = OFF_LX + (size_t)BQ*CC;

    cudaFuncSetAttribute(k2b_decay, cudaFuncAttributeMaxDynamicSharedMemorySize, K2B_SMEM_BYTES);
    cudaFuncSetAttribute(k5_intra,  cudaFuncAttributeMaxDynamicSharedMemorySize, K5_SMEM_BYTES);
    cudaFuncSetAttribute(k6_out,    cudaFuncAttributeMaxDynamicSharedMemorySize, K6_SMEM_BYTES);

    k1_mix    <<<MTOK/32, 256>>>(hs, shift, maa_x, w1);
    k1b_abuild<<<dim3(MTOK/64, CC/64), 256>>>(hs, shift, maa_w, maa_k, maa_v,
                                              maa_r, maa_g, w2);
    k2_gemm   <<<dim3(MTOK/128, 5), 256>>>(dw1, Wk, Wv, Wr, Wg);
    k2b_decay <<<MTOK/128, 256, K2B_SMEM_BYTES>>>(dw2, tdecay);
    k3_chunk  <<<BQ*NCH, 256>>>();
    k4_scan   <<<32, 256>>>(wkv0, out + OFF_SF);
    k5_intra  <<<BQ*NCH, 256, K5_SMEM_BYTES>>>(faaaa);
    k6_out    <<<dim3(MTOK/128, CC/128), 256, K6_SMEM_BYTES>>>(Wo, out);
    k7_lx     <<<8, 512>>>(hs, out + OFF_LX);
}